// round 2
// baseline (speedup 1.0000x reference)
#include <cuda_runtime.h>
#include <math.h>

#define BB 32
#define SS 512
#define II 512
#define HH 1024
#define G3 3072
#define H2 2048
#define CHUNK_SM (128 * 64)   // W chunk floats in smem: 128 kl x 8 jp x 8(pad)

// ---------------- device scratch ----------------
__device__ float g_wih0_t[2][II * G3];
__device__ float g_wih1_t[2][(size_t)H2 * G3];
__device__ float g_whh_t[2][2][HH * G3];
__device__ float g_gx[2][(size_t)BB * SS * G3];
__device__ float g_h[2][2][BB * HH];
__device__ float g_out0[(size_t)BB * SS * H2];
__device__ unsigned g_bar_count[2];
__device__ unsigned g_bar_gen[2];

// ---------------- packed fp32x2 FMA ----------------
__device__ __forceinline__ float2 ffma2(float2 a, float2 b, float2 c) {
    unsigned long long A = *reinterpret_cast<unsigned long long*>(&a);
    unsigned long long B = *reinterpret_cast<unsigned long long*>(&b);
    unsigned long long C = *reinterpret_cast<unsigned long long*>(&c);
    unsigned long long D;
    asm("fma.rn.f32x2 %0, %1, %2, %3;" : "=l"(D) : "l"(A), "l"(B), "l"(C));
    return *reinterpret_cast<float2*>(&D);
}

__device__ __forceinline__ float sigmoidf_(float x) { return 1.0f / (1.0f + expf(-x)); }

// software grid barrier scoped to one direction (64 CTAs)
__device__ __forceinline__ void dir_barrier(int dir) {
    __syncthreads();
    if (threadIdx.x == 0) {
        volatile unsigned* genp = &g_bar_gen[dir];
        unsigned gen = *genp;
        __threadfence();
        if (atomicAdd(&g_bar_count[dir], 1u) == 63u) {
            g_bar_count[dir] = 0;
            __threadfence();
            atomicAdd((unsigned*)genp, 1u);
        } else {
            while (*genp == gen) { __nanosleep(64); }
            __threadfence();
        }
    }
    __syncthreads();
}

// ---------------- transpose: in[3072][K] -> out[K][3072] ----------------
__global__ void transpose_w(const float* __restrict__ in, float* __restrict__ out, int K) {
    __shared__ float tile[32][33];
    int n0 = blockIdx.x * 32, k0 = blockIdx.y * 32;
    for (int i = threadIdx.y; i < 32; i += 8)
        tile[i][threadIdx.x] = in[(size_t)(n0 + i) * K + k0 + threadIdx.x];
    __syncthreads();
    for (int i = threadIdx.y; i < 32; i += 8)
        out[(size_t)(k0 + i) * G3 + n0 + threadIdx.x] = tile[threadIdx.x][i];
}

// ---------------- SGEMM: C[m][n] = sum_k Xrow(m)[k]*Wt[k][n] + bias[n] ----------------
__global__ __launch_bounds__(256) void gemm_gx(
    const float* __restrict__ X, int strideB, int strideS, int K,
    const float* __restrict__ Wt, const float* __restrict__ bias,
    float* __restrict__ C)
{
    __shared__ float As[16][64];
    __shared__ float Bs[16][128];
    int bn = blockIdx.x * 128;
    int bm = blockIdx.y * 64;
    int tid = threadIdx.x;
    int tx = tid & 15, ty = tid >> 4;

    int rowA = tid >> 2;
    int kq   = tid & 3;
    int m = bm + rowA;
    int sb_s = m >> 5, sb_b = m & 31;
    const float* Xrow = X + (size_t)sb_b * strideB + (size_t)sb_s * strideS;

    float2 acc[4][4];
#pragma unroll
    for (int i = 0; i < 4; i++)
#pragma unroll
        for (int j = 0; j < 4; j++) acc[i][j] = make_float2(0.f, 0.f);

    for (int k0 = 0; k0 < K; k0 += 16) {
        float4 av = *(const float4*)(Xrow + k0 + kq * 4);
        float4 bv0, bv1;
        {
            int idx = tid;
            int kr = idx >> 5, nq = idx & 31;
            bv0 = *(const float4*)(Wt + (size_t)(k0 + kr) * G3 + bn + nq * 4);
            idx = tid + 256;
            kr = idx >> 5; nq = idx & 31;
            bv1 = *(const float4*)(Wt + (size_t)(k0 + kr) * G3 + bn + nq * 4);
        }
        __syncthreads();
        As[kq * 4 + 0][rowA] = av.x;
        As[kq * 4 + 1][rowA] = av.y;
        As[kq * 4 + 2][rowA] = av.z;
        As[kq * 4 + 3][rowA] = av.w;
        {
            int idx = tid;
            int kr = idx >> 5, nq = idx & 31;
            *(float4*)&Bs[kr][nq * 4] = bv0;
            idx = tid + 256; kr = idx >> 5; nq = idx & 31;
            *(float4*)&Bs[kr][nq * 4] = bv1;
        }
        __syncthreads();
#pragma unroll
        for (int kk = 0; kk < 16; kk++) {
            float4 a  = *(const float4*)&As[kk][ty * 4];
            float4 b0 = *(const float4*)&Bs[kk][tx * 8];
            float4 b1 = *(const float4*)&Bs[kk][tx * 8 + 4];
            float aa[4] = {a.x, a.y, a.z, a.w};
            float2 bb[4] = {make_float2(b0.x, b0.y), make_float2(b0.z, b0.w),
                            make_float2(b1.x, b1.y), make_float2(b1.z, b1.w)};
#pragma unroll
            for (int i = 0; i < 4; i++) {
                float2 a2 = make_float2(aa[i], aa[i]);
#pragma unroll
                for (int j = 0; j < 4; j++) acc[i][j] = ffma2(a2, bb[j], acc[i][j]);
            }
        }
    }
#pragma unroll
    for (int i = 0; i < 4; i++) {
        int m2 = bm + ty * 4 + i;
        float* crow = C + (size_t)m2 * G3 + bn + tx * 8;
#pragma unroll
        for (int j = 0; j < 4; j++) {
            int n = bn + tx * 8 + j * 2;
            float2 v = acc[i][j];
            v.x += bias[n];
            v.y += bias[n + 1];
            *(float2*)(crow + j * 2) = v;
        }
    }
}

// ---------------- persistent recurrent layer ----------------
// grid (64 jblks, 2 dirs), 256 thr = 32 b x 8 jp, 2 cols/thread.
// SMEM: h [32][1025] + double-buffered W chunk [2][128][8jp][8pad].
#define STEP_SMEM_FLOATS (32 * 1025 + 2 * CHUNK_SM)

__global__ __launch_bounds__(256, 1) void gru_layer(
    int layer, const float* __restrict__ bhh_f, const float* __restrict__ bhh_b)
{
    extern __shared__ float smem[];
    float* h_sh = smem;                     // 32*1025
    float* ws   = smem + 32 * 1025;         // 2 * CHUNK_SM

    const int dir  = blockIdx.y;
    const int jblk = blockIdx.x;
    const int tid  = threadIdx.x;
    const int b  = tid >> 3;
    const int jp = tid & 7;
    const int j0 = jblk * 16 + jp * 2;
    const int jcol = jblk * 16;

    const float* wt  = g_whh_t[layer][dir];
    const float* bhh = dir ? bhh_b : bhh_f;
    const float* gx_base = g_gx[dir];

    const float2 br  = *(const float2*)(bhh + j0);
    const float2 bz  = *(const float2*)(bhh + HH + j0);
    const float2 bn2 = *(const float2*)(bhh + 2 * HH + j0);

    for (int t = 0; t < SS; t++) {
        const float* hprev = g_h[dir][t & 1];
        // stage h_prev into padded smem
        for (int i = tid; i < 8192; i += 256) {
            float4 v = *(const float4*)(hprev + i * 4);
            int bi = (i * 4) >> 10;
            int k  = (i * 4) & 1023;
            float* d = &h_sh[bi * 1025 + k];
            d[0] = v.x; d[1] = v.y; d[2] = v.z; d[3] = v.w;
        }
        // prefetch gx (DRAM) early — consumed only at gate math
        const int s_sel = dir ? (SS - 1 - t) : t;
        const float* gxp = gx_base + ((size_t)s_sel * BB + b) * G3 + j0;
        const float2 xr = *(const float2*)(gxp);
        const float2 xz = *(const float2*)(gxp + HH);
        const float2 xn = *(const float2*)(gxp + 2 * HH);

        // prefetch W chunk 0 into regs
        float pre[24];
#pragma unroll
        for (int r = 0; r < 24; r++) {
            int idx = r * 256 + tid;
            int kl = idx / 48, cc = idx % 48;
            int jpp = cc / 6, e = cc % 6;
            pre[r] = wt[(size_t)kl * G3 + (e >> 1) * HH + jcol + jpp * 2 + (e & 1)];
        }

        float2 accr = make_float2(0.f, 0.f), accz = accr, accn = accr;
        int buf = 0;
        for (int c = 0; c < 8; c++) {
            float* wbuf = ws + buf * CHUNK_SM;
#pragma unroll
            for (int r = 0; r < 24; r++) {
                int idx = r * 256 + tid;
                int kl = idx / 48, cc = idx % 48;
                int jpp = cc / 6, e = cc % 6;
                wbuf[kl * 64 + jpp * 8 + e] = pre[r];
            }
            __syncthreads();
            if (c < 7) {
                int k0n = (c + 1) * 128;
#pragma unroll
                for (int r = 0; r < 24; r++) {
                    int idx = r * 256 + tid;
                    int kl = idx / 48, cc = idx % 48;
                    int jpp = cc / 6, e = cc % 6;
                    pre[r] = wt[(size_t)(k0n + kl) * G3 + (e >> 1) * HH + jcol + jpp * 2 + (e & 1)];
                }
            }
            const float* hrow = &h_sh[b * 1025 + c * 128];
            const float* wq = wbuf + jp * 8;
#pragma unroll 8
            for (int kl = 0; kl < 128; kl++) {
                float hk = hrow[kl];
                float2 h2 = make_float2(hk, hk);
                float4 wa  = *(const float4*)(wq + kl * 64);
                float2 wb2 = *(const float2*)(wq + kl * 64 + 4);
                accr = ffma2(h2, make_float2(wa.x, wa.y), accr);
                accz = ffma2(h2, make_float2(wa.z, wa.w), accz);
                accn = ffma2(h2, wb2, accn);
            }
            buf ^= 1;
        }

        // gate math
        float hp0 = h_sh[b * 1025 + j0];
        float hp1 = h_sh[b * 1025 + j0 + 1];
        float r0 = sigmoidf_(xr.x + accr.x + br.x);
        float r1 = sigmoidf_(xr.y + accr.y + br.y);
        float z0 = sigmoidf_(xz.x + accz.x + bz.x);
        float z1 = sigmoidf_(xz.y + accz.y + bz.y);
        float n0 = tanhf(xn.x + r0 * (accn.x + bn2.x));
        float n1 = tanhf(xn.y + r1 * (accn.y + bn2.y));
        float h0n = (1.f - z0) * n0 + z0 * hp0;
        float h1n = (1.f - z1) * n1 + z1 * hp1;

        float* hout = g_h[dir][(t + 1) & 1];
        *(float2*)(hout + b * HH + j0) = make_float2(h0n, h1n);
        if (layer == 0)
            *(float2*)(&g_out0[((size_t)b * SS + s_sel) * H2 + dir * HH + j0]) =
                make_float2(h0n, h1n);

        dir_barrier(dir);
    }
}

// ---------------- zero hidden (parity 0, both dirs) ----------------
__global__ void zero_h_k() {
    int i = blockIdx.x * blockDim.x + threadIdx.x;
    if (i < BB * HH) { g_h[0][0][i] = 0.f; g_h[1][0][i] = 0.f; }
}

// ---------------- final output ----------------
__global__ void finalize_k(float* __restrict__ out) {
    int i = blockIdx.x * blockDim.x + threadIdx.x;
    if (i < BB * H2) {
        int b = i >> 11, c = i & 2047;
        out[i] = (c < HH) ? g_h[0][0][b * HH + c] : g_h[1][0][b * HH + c - HH];
    }
}

// ---------------- host ----------------
extern "C" void kernel_launch(void* const* d_in, const int* in_sizes, int n_in,
                              void* d_out, int out_size)
{
    const float* x       = (const float*)d_in[0];
    const float* w_ih_f0 = (const float*)d_in[1];
    const float* w_hh_f0 = (const float*)d_in[2];
    const float* b_ih_f0 = (const float*)d_in[3];
    const float* b_hh_f0 = (const float*)d_in[4];
    const float* w_ih_b0 = (const float*)d_in[5];
    const float* w_hh_b0 = (const float*)d_in[6];
    const float* b_ih_b0 = (const float*)d_in[7];
    const float* b_hh_b0 = (const float*)d_in[8];
    const float* w_ih_f1 = (const float*)d_in[9];
    const float* w_hh_f1 = (const float*)d_in[10];
    const float* b_ih_f1 = (const float*)d_in[11];
    const float* b_hh_f1 = (const float*)d_in[12];
    const float* w_ih_b1 = (const float*)d_in[13];
    const float* w_hh_b1 = (const float*)d_in[14];
    const float* b_ih_b1 = (const float*)d_in[15];
    const float* b_hh_b1 = (const float*)d_in[16];
    float* out = (float*)d_out;

    size_t step_smem = STEP_SMEM_FLOATS * sizeof(float);
    cudaFuncSetAttribute(gru_layer, cudaFuncAttributeMaxDynamicSharedMemorySize,
                         (int)step_smem);

    float *wih0, *wih1, *whh, *gx, *out0;
    cudaGetSymbolAddress((void**)&wih0, g_wih0_t);
    cudaGetSymbolAddress((void**)&wih1, g_wih1_t);
    cudaGetSymbolAddress((void**)&whh,  g_whh_t);
    cudaGetSymbolAddress((void**)&gx,   g_gx);
    cudaGetSymbolAddress((void**)&out0, g_out0);

    float* wih0_f = wih0;
    float* wih0_b = wih0 + (size_t)II * G3;
    float* wih1_f = wih1;
    float* wih1_b = wih1 + (size_t)H2 * G3;
    float* whh_00 = whh;
    float* whh_01 = whh + (size_t)HH * G3;
    float* whh_10 = whh + 2 * (size_t)HH * G3;
    float* whh_11 = whh + 3 * (size_t)HH * G3;
    float* gx_f = gx;
    float* gx_b = gx + (size_t)BB * SS * G3;

    dim3 tb(32, 8);
    transpose_w<<<dim3(96, II / 32), tb>>>(w_ih_f0, wih0_f, II);
    transpose_w<<<dim3(96, II / 32), tb>>>(w_ih_b0, wih0_b, II);
    transpose_w<<<dim3(96, HH / 32), tb>>>(w_hh_f0, whh_00, HH);
    transpose_w<<<dim3(96, HH / 32), tb>>>(w_hh_b0, whh_01, HH);
    transpose_w<<<dim3(96, HH / 32), tb>>>(w_hh_f1, whh_10, HH);
    transpose_w<<<dim3(96, HH / 32), tb>>>(w_hh_b1, whh_11, HH);
    transpose_w<<<dim3(96, H2 / 32), tb>>>(w_ih_f1, wih1_f, H2);
    transpose_w<<<dim3(96, H2 / 32), tb>>>(w_ih_b1, wih1_b, H2);

    // ---- layer 0 ----
    zero_h_k<<<(BB * HH + 255) / 256, 256>>>();
    dim3 ggrid(G3 / 128, (BB * SS) / 64);
    gemm_gx<<<ggrid, 256>>>(x, SS * II, II, II, wih0_f, b_ih_f0, gx_f);
    gemm_gx<<<ggrid, 256>>>(x, SS * II, II, II, wih0_b, b_ih_b0, gx_b);

    gru_layer<<<dim3(64, 2), 256, step_smem>>>(0, b_hh_f0, b_hh_b0);

    // ---- layer 1 ----
    gemm_gx<<<ggrid, 256>>>(out0, SS * H2, H2, H2, wih1_f, b_ih_f1, gx_f);
    gemm_gx<<<ggrid, 256>>>(out0, SS * H2, H2, H2, wih1_b, b_ih_b1, gx_b);
    zero_h_k<<<(BB * HH + 255) / 256, 256>>>();
    gru_layer<<<dim3(64, 2), 256, step_smem>>>(1, b_hh_f1, b_hh_b1);

    finalize_k<<<(BB * H2 + 255) / 256, 256>>>(out);
}

// round 3
// speedup vs baseline: 1.7076x; 1.7076x over previous
#include <cuda_runtime.h>
#include <math.h>

#define BB 32
#define SS 512
#define II 512
#define HH 1024
#define G3 3072
#define H2 2048

#define W_SM_FLOATS (512 * 96)          // per-CTA W slice: 512 kp x 96 = 49152 floats
#define HBUF_STRIDE 132                 // 128 + 4 pad, 16B-aligned stride
#define GRU_SMEM_FLOATS (W_SM_FLOATS + 2 * 32 * HBUF_STRIDE)   // 57600 floats = 230400 B

// ---------------- device scratch ----------------
__device__ float g_wih0_t[2][II * G3];
__device__ float g_wih1_t[2][(size_t)H2 * G3];
__device__ float g_whh_p[2][2][HH * G3];          // packed per-CTA W_hh
__device__ float g_gx[2][(size_t)BB * SS * G3];
__device__ float g_h[2][2][BB * HH];
__device__ float g_out0[(size_t)BB * SS * H2];
__device__ unsigned g_bar_count[2];
__device__ unsigned g_bar_gen[2];

// ---------------- helpers ----------------
__device__ __forceinline__ float2 ffma2(float2 a, float2 b, float2 c) {
    unsigned long long A = *reinterpret_cast<unsigned long long*>(&a);
    unsigned long long B = *reinterpret_cast<unsigned long long*>(&b);
    unsigned long long C = *reinterpret_cast<unsigned long long*>(&c);
    unsigned long long D;
    asm("fma.rn.f32x2 %0, %1, %2, %3;" : "=l"(D) : "l"(A), "l"(B), "l"(C));
    return *reinterpret_cast<float2*>(&D);
}

__device__ __forceinline__ float sigmoidf_(float x) { return 1.0f / (1.0f + expf(-x)); }

__device__ __forceinline__ float4 ldcg4(const float* p) {
    float4 v;
    asm volatile("ld.global.cg.v4.f32 {%0,%1,%2,%3}, [%4];"
                 : "=f"(v.x), "=f"(v.y), "=f"(v.z), "=f"(v.w) : "l"(p));
    return v;
}
__device__ __forceinline__ float2 ldcg2(const float* p) {
    float2 v;
    asm volatile("ld.global.cg.v2.f32 {%0,%1}, [%2];" : "=f"(v.x), "=f"(v.y) : "l"(p));
    return v;
}

// grid barrier per direction (64 CTAs), monotonic count, no reset race
__device__ __forceinline__ void dir_barrier(int dir, unsigned n) {
    __syncthreads();
    if (threadIdx.x == 0) {
        unsigned* cnt = &g_bar_count[dir];
        unsigned* gen = &g_bar_gen[dir];
        unsigned old;
        asm volatile("atom.acq_rel.gpu.global.add.u32 %0, [%1], 1;"
                     : "=r"(old) : "l"(cnt) : "memory");
        if (old == n * 64u - 1u) {
            asm volatile("red.release.gpu.global.add.u32 [%0], 1;" :: "l"(gen) : "memory");
        } else {
            unsigned cur;
            do {
                __nanosleep(32);
                asm volatile("ld.acquire.gpu.global.u32 %0, [%1];"
                             : "=r"(cur) : "l"(gen) : "memory");
            } while (cur < n);
        }
    }
    __syncthreads();
}

// ---------------- batched transpose for w_ih: in[3072][K] -> out[K][3072] ----------------
__global__ void transpose_ih(const float* f0, const float* b0,
                             const float* f1, const float* b1,
                             float* df0, float* db0, float* df1, float* db1) {
    __shared__ float tile[32][33];
    const float* in; float* out; int K;
    switch (blockIdx.z) {
        case 0: in = f0; out = df0; K = II; break;
        case 1: in = b0; out = db0; K = II; break;
        case 2: in = f1; out = df1; K = H2; break;
        default: in = b1; out = db1; K = H2; break;
    }
    int n0 = blockIdx.x * 32, k0 = blockIdx.y * 32;
    if (k0 >= K) return;
    for (int i = threadIdx.y; i < 32; i += 8)
        tile[i][threadIdx.x] = in[(size_t)(n0 + i) * K + k0 + threadIdx.x];
    __syncthreads();
    for (int i = threadIdx.y; i < 32; i += 8)
        out[(size_t)(k0 + i) * G3 + n0 + threadIdx.x] = tile[threadIdx.x][i];
}

// ---------------- prepack W_hh into per-CTA layout ----------------
// dst[jblk][kp][g][jp][kk][c] = w_hh[g*1024 + jblk*16 + jp*2 + c][kp*2 + kk]
__global__ void prepack_whh(const float* w00, const float* w01,
                            const float* w10, const float* w11) {
    int mat = blockIdx.y;
    const float* src = (mat == 0) ? w00 : (mat == 1) ? w01 : (mat == 2) ? w10 : w11;
    float* dst = g_whh_p[mat >> 1][mat & 1];
    int idx = blockIdx.x * 256 + threadIdx.x;          // 0 .. 3145727
    int jblk = idx / 49152;
    int rem  = idx - jblk * 49152;
    int kp = rem / 96;
    int q  = rem - kp * 96;
    int g  = q >> 5;
    int q2 = q & 31;
    int jp = q2 >> 2;
    int q3 = q2 & 3;
    int kk = q3 >> 1;
    int c  = q3 & 1;
    int n = g * 1024 + jblk * 16 + jp * 2 + c;
    int k = kp * 2 + kk;
    dst[idx] = src[(size_t)n * HH + k];
}

// ---------------- SGEMM: C[m][n] = sum_k Xrow(m)[k]*Wt[k][n] + bias[n] ----------------
__global__ __launch_bounds__(256) void gemm_gx(
    const float* __restrict__ X, int strideB, int strideS, int K,
    const float* __restrict__ Wt, const float* __restrict__ bias,
    float* __restrict__ C)
{
    __shared__ float As[16][64];
    __shared__ float Bs[16][128];
    int bn = blockIdx.x * 128;
    int bm = blockIdx.y * 64;
    int tid = threadIdx.x;
    int tx = tid & 15, ty = tid >> 4;

    int rowA = tid >> 2;
    int kq   = tid & 3;
    int m = bm + rowA;
    int sb_s = m >> 5, sb_b = m & 31;
    const float* Xrow = X + (size_t)sb_b * strideB + (size_t)sb_s * strideS;

    float2 acc[4][4];
#pragma unroll
    for (int i = 0; i < 4; i++)
#pragma unroll
        for (int j = 0; j < 4; j++) acc[i][j] = make_float2(0.f, 0.f);

    for (int k0 = 0; k0 < K; k0 += 16) {
        float4 av = *(const float4*)(Xrow + k0 + kq * 4);
        float4 bv0, bv1;
        {
            int idx = tid;
            int kr = idx >> 5, nq = idx & 31;
            bv0 = *(const float4*)(Wt + (size_t)(k0 + kr) * G3 + bn + nq * 4);
            idx = tid + 256;
            kr = idx >> 5; nq = idx & 31;
            bv1 = *(const float4*)(Wt + (size_t)(k0 + kr) * G3 + bn + nq * 4);
        }
        __syncthreads();
        As[kq * 4 + 0][rowA] = av.x;
        As[kq * 4 + 1][rowA] = av.y;
        As[kq * 4 + 2][rowA] = av.z;
        As[kq * 4 + 3][rowA] = av.w;
        {
            int idx = tid;
            int kr = idx >> 5, nq = idx & 31;
            *(float4*)&Bs[kr][nq * 4] = bv0;
            idx = tid + 256; kr = idx >> 5; nq = idx & 31;
            *(float4*)&Bs[kr][nq * 4] = bv1;
        }
        __syncthreads();
#pragma unroll
        for (int kk = 0; kk < 16; kk++) {
            float4 a  = *(const float4*)&As[kk][ty * 4];
            float4 b0 = *(const float4*)&Bs[kk][tx * 8];
            float4 b1 = *(const float4*)&Bs[kk][tx * 8 + 4];
            float aa[4] = {a.x, a.y, a.z, a.w};
            float2 bb[4] = {make_float2(b0.x, b0.y), make_float2(b0.z, b0.w),
                            make_float2(b1.x, b1.y), make_float2(b1.z, b1.w)};
#pragma unroll
            for (int i = 0; i < 4; i++) {
                float2 a2 = make_float2(aa[i], aa[i]);
#pragma unroll
                for (int j = 0; j < 4; j++) acc[i][j] = ffma2(a2, bb[j], acc[i][j]);
            }
        }
    }
#pragma unroll
    for (int i = 0; i < 4; i++) {
        int m2 = bm + ty * 4 + i;
        float* crow = C + (size_t)m2 * G3 + bn + tx * 8;
#pragma unroll
        for (int j = 0; j < 4; j++) {
            int n = bn + tx * 8 + j * 2;
            float2 v = acc[i][j];
            v.x += bias[n];
            v.y += bias[n + 1];
            *(float2*)(crow + j * 2) = v;
        }
    }
}

// ---------------- persistent recurrent layer (W resident in SMEM) ----------------
// grid (64 jblks, 2 dirs), 256 thr = 32 b x 8 jp, 2 cols/thread.
__global__ __launch_bounds__(256, 1) void gru_layer(
    int layer, const float* __restrict__ bhh_f, const float* __restrict__ bhh_b)
{
    extern __shared__ float smem[];
    float* wsm   = smem;                       // 49152 floats
    float* hbuf0 = smem + W_SM_FLOATS;         // 2 x 32 x 132

    const int dir  = blockIdx.y;
    const int jblk = blockIdx.x;
    const int tid  = threadIdx.x;
    const int b  = tid >> 3;
    const int jp = tid & 7;
    const int j0 = jblk * 16 + jp * 2;

    // stage this CTA's W slice once (coalesced float4)
    const float* wsrc = g_whh_p[layer][dir] + (size_t)jblk * W_SM_FLOATS;
    for (int i = tid; i < W_SM_FLOATS / 4; i += 256)
        *(float4*)&wsm[i * 4] = *(const float4*)&wsrc[i * 4];

    const float* bhh = dir ? bhh_b : bhh_f;
    const float2 br  = *(const float2*)(bhh + j0);
    const float2 bz  = *(const float2*)(bhh + HH + j0);
    const float2 bn2 = *(const float2*)(bhh + 2 * HH + j0);
    const float* gx_base = g_gx[dir];
    __syncthreads();

    for (int t = 0; t < SS; t++) {
        const float* hprev = g_h[dir][t & 1];
        const int s_sel = dir ? (SS - 1 - t) : t;

        // prefetch gx + own h_prev (consumed at gate math)
        const float* gxp = gx_base + ((size_t)s_sel * BB + b) * G3 + j0;
        const float2 xr = ldcg2(gxp);
        const float2 xz = ldcg2(gxp + HH);
        const float2 xn = ldcg2(gxp + 2 * HH);
        const float2 hp = ldcg2(hprev + b * HH + j0);

        // prefetch h chunk 0 into regs (L2-coherent)
        float4 hr[4];
#pragma unroll
        for (int j = 0; j < 4; j++) {
            int f = j * 256 + tid;
            hr[j] = ldcg4(hprev + (f >> 5) * HH + (f & 31) * 4);
        }

        float2 accr = make_float2(0.f, 0.f), accz = accr, accn = accr;
        int buf = 0;
        for (int c = 0; c < 8; c++) {
            float* hb = hbuf0 + buf * (32 * HBUF_STRIDE);
#pragma unroll
            for (int j = 0; j < 4; j++) {
                int f = j * 256 + tid;
                *(float4*)&hb[(f >> 5) * HBUF_STRIDE + (f & 31) * 4] = hr[j];
            }
            __syncthreads();
            if (c < 7) {
#pragma unroll
                for (int j = 0; j < 4; j++) {
                    int f = j * 256 + tid;
                    hr[j] = ldcg4(hprev + (f >> 5) * HH + (c + 1) * 128 + (f & 31) * 4);
                }
            }
            const float* hrow  = hb + b * HBUF_STRIDE;
            const float* wbase = wsm + (c * 64) * 96 + jp * 4;
#pragma unroll 8
            for (int kp4 = 0; kp4 < 32; kp4++) {
                float4 h4 = *(const float4*)&hrow[kp4 * 4];
                const float* w0 = wbase + (kp4 * 2) * 96;
                float4 wr0 = *(const float4*)(w0);
                float4 wz0 = *(const float4*)(w0 + 32);
                float4 wn0 = *(const float4*)(w0 + 64);
                accr = ffma2(make_float2(h4.x, h4.x), make_float2(wr0.x, wr0.y), accr);
                accr = ffma2(make_float2(h4.y, h4.y), make_float2(wr0.z, wr0.w), accr);
                accz = ffma2(make_float2(h4.x, h4.x), make_float2(wz0.x, wz0.y), accz);
                accz = ffma2(make_float2(h4.y, h4.y), make_float2(wz0.z, wz0.w), accz);
                accn = ffma2(make_float2(h4.x, h4.x), make_float2(wn0.x, wn0.y), accn);
                accn = ffma2(make_float2(h4.y, h4.y), make_float2(wn0.z, wn0.w), accn);
                const float* w1 = w0 + 96;
                float4 wr1 = *(const float4*)(w1);
                float4 wz1 = *(const float4*)(w1 + 32);
                float4 wn1 = *(const float4*)(w1 + 64);
                accr = ffma2(make_float2(h4.z, h4.z), make_float2(wr1.x, wr1.y), accr);
                accr = ffma2(make_float2(h4.w, h4.w), make_float2(wr1.z, wr1.w), accr);
                accz = ffma2(make_float2(h4.z, h4.z), make_float2(wz1.x, wz1.y), accz);
                accz = ffma2(make_float2(h4.w, h4.w), make_float2(wz1.z, wz1.w), accz);
                accn = ffma2(make_float2(h4.z, h4.z), make_float2(wn1.x, wn1.y), accn);
                accn = ffma2(make_float2(h4.w, h4.w), make_float2(wn1.z, wn1.w), accn);
            }
            buf ^= 1;
        }

        // gate math
        float r0 = sigmoidf_(xr.x + accr.x + br.x);
        float r1 = sigmoidf_(xr.y + accr.y + br.y);
        float z0 = sigmoidf_(xz.x + accz.x + bz.x);
        float z1 = sigmoidf_(xz.y + accz.y + bz.y);
        float n0 = tanhf(xn.x + r0 * (accn.x + bn2.x));
        float n1 = tanhf(xn.y + r1 * (accn.y + bn2.y));
        float h0n = (1.f - z0) * n0 + z0 * hp.x;
        float h1n = (1.f - z1) * n1 + z1 * hp.y;

        float* hout = g_h[dir][(t + 1) & 1];
        *(float2*)(hout + b * HH + j0) = make_float2(h0n, h1n);
        if (layer == 0)
            *(float2*)(&g_out0[((size_t)b * SS + s_sel) * H2 + dir * HH + j0]) =
                make_float2(h0n, h1n);

        dir_barrier(dir, (unsigned)(t + 1));
    }
}

// ---------------- zero hidden + barrier state ----------------
__global__ void zero_h_k() {
    int i = blockIdx.x * blockDim.x + threadIdx.x;
    if (i < BB * HH) { g_h[0][0][i] = 0.f; g_h[1][0][i] = 0.f; }
    if (i < 2) { g_bar_count[i] = 0u; g_bar_gen[i] = 0u; }
}

// ---------------- final output ----------------
__global__ void finalize_k(float* __restrict__ out) {
    int i = blockIdx.x * blockDim.x + threadIdx.x;
    if (i < BB * H2) {
        int b = i >> 11, c = i & 2047;
        out[i] = (c < HH) ? g_h[0][0][b * HH + c] : g_h[1][0][b * HH + c - HH];
    }
}

// ---------------- host ----------------
extern "C" void kernel_launch(void* const* d_in, const int* in_sizes, int n_in,
                              void* d_out, int out_size)
{
    const float* x       = (const float*)d_in[0];
    const float* w_ih_f0 = (const float*)d_in[1];
    const float* w_hh_f0 = (const float*)d_in[2];
    const float* b_ih_f0 = (const float*)d_in[3];
    const float* b_hh_f0 = (const float*)d_in[4];
    const float* w_ih_b0 = (const float*)d_in[5];
    const float* w_hh_b0 = (const float*)d_in[6];
    const float* b_ih_b0 = (const float*)d_in[7];
    const float* b_hh_b0 = (const float*)d_in[8];
    const float* w_ih_f1 = (const float*)d_in[9];
    const float* w_hh_f1 = (const float*)d_in[10];
    const float* b_ih_f1 = (const float*)d_in[11];
    const float* b_hh_f1 = (const float*)d_in[12];
    const float* w_ih_b1 = (const float*)d_in[13];
    const float* w_hh_b1 = (const float*)d_in[14];
    const float* b_ih_b1 = (const float*)d_in[15];
    const float* b_hh_b1 = (const float*)d_in[16];
    float* out = (float*)d_out;

    size_t gru_smem = GRU_SMEM_FLOATS * sizeof(float);
    cudaFuncSetAttribute(gru_layer, cudaFuncAttributeMaxDynamicSharedMemorySize,
                         (int)gru_smem);

    float *wih0, *wih1, *gx, *out0;
    cudaGetSymbolAddress((void**)&wih0, g_wih0_t);
    cudaGetSymbolAddress((void**)&wih1, g_wih1_t);
    cudaGetSymbolAddress((void**)&gx,   g_gx);
    cudaGetSymbolAddress((void**)&out0, g_out0);

    float* wih0_f = wih0;
    float* wih0_b = wih0 + (size_t)II * G3;
    float* wih1_f = wih1;
    float* wih1_b = wih1 + (size_t)H2 * G3;
    float* gx_f = gx;
    float* gx_b = gx + (size_t)BB * SS * G3;

    // L1: batched w_ih transpose (4 matrices)
    transpose_ih<<<dim3(96, 64, 4), dim3(32, 8)>>>(
        w_ih_f0, w_ih_b0, w_ih_f1, w_ih_b1, wih0_f, wih0_b, wih1_f, wih1_b);
    // L2: prepack all 4 w_hh
    prepack_whh<<<dim3(12288, 4), 256>>>(w_hh_f0, w_hh_b0, w_hh_f1, w_hh_b1);
    // L3: zero h + barriers
    zero_h_k<<<(BB * HH + 255) / 256, 256>>>();
    // L4, L5: layer0 gx GEMMs
    dim3 ggrid(G3 / 128, (BB * SS) / 64);
    gemm_gx<<<ggrid, 256>>>(x, SS * II, II, II, wih0_f, b_ih_f0, gx_f);
    gemm_gx<<<ggrid, 256>>>(x, SS * II, II, II, wih0_b, b_ih_b0, gx_b);
    // L6: layer0 recurrence (ncu -s 5 -c 1 profiles this one)
    gru_layer<<<dim3(64, 2), 256, gru_smem>>>(0, b_hh_f0, b_hh_b0);

    // layer 1
    gemm_gx<<<ggrid, 256>>>(out0, SS * H2, H2, H2, wih1_f, b_ih_f1, gx_f);
    gemm_gx<<<ggrid, 256>>>(out0, SS * H2, H2, H2, wih1_b, b_ih_b1, gx_b);
    zero_h_k<<<(BB * HH + 255) / 256, 256>>>();
    gru_layer<<<dim3(64, 2), 256, gru_smem>>>(1, b_hh_f1, b_hh_b1);

    finalize_k<<<(BB * H2 + 255) / 256, 256>>>(out);
}

// round 4
// speedup vs baseline: 1.9698x; 1.1535x over previous
#include <cuda_runtime.h>
#include <math.h>

#define BB 32
#define SS 512
#define II 512
#define HH 1024
#define G3 3072
#define H2 2048

#define W_SM_FLOATS (512 * 96)        // per-CTA W slice (196,608 B)
#define HCHUNK 64                     // k per staged chunk
#define HSTRIDE 68                    // 64 + 4 pad
#define HBUF_FLOATS (32 * HSTRIDE)    // 2176 floats per buffer
#define GRU_SMEM_FLOATS (W_SM_FLOATS + 4 * HBUF_FLOATS)   // 57856 floats = 231,424 B

// ---------------- device scratch ----------------
__device__ float g_wih0_t[2][II * G3];
__device__ float g_wih1_t[2][(size_t)H2 * G3];
__device__ float g_whh_p[2][2][HH * G3];
__device__ float g_gx[2][(size_t)BB * SS * G3];
__device__ float g_h[2][2][BB * HH];
__device__ float g_out0[(size_t)BB * SS * H2];
__device__ unsigned g_bar_count[2];
__device__ unsigned g_bar_gen[2];

// ---------------- helpers ----------------
__device__ __forceinline__ float2 ffma2(float2 a, float2 b, float2 c) {
    unsigned long long A = *reinterpret_cast<unsigned long long*>(&a);
    unsigned long long B = *reinterpret_cast<unsigned long long*>(&b);
    unsigned long long C = *reinterpret_cast<unsigned long long*>(&c);
    unsigned long long D;
    asm("fma.rn.f32x2 %0, %1, %2, %3;" : "=l"(D) : "l"(A), "l"(B), "l"(C));
    return *reinterpret_cast<float2*>(&D);
}

__device__ __forceinline__ float sigmoidf_(float x) { return 1.0f / (1.0f + expf(-x)); }

__device__ __forceinline__ float4 ldcg4(const float* p) {
    float4 v;
    asm volatile("ld.global.cg.v4.f32 {%0,%1,%2,%3}, [%4];"
                 : "=f"(v.x), "=f"(v.y), "=f"(v.z), "=f"(v.w) : "l"(p));
    return v;
}
__device__ __forceinline__ float2 ldcg2(const float* p) {
    float2 v;
    asm volatile("ld.global.cg.v2.f32 {%0,%1}, [%2];" : "=f"(v.x), "=f"(v.y) : "l"(p));
    return v;
}

// grid barrier per direction (64 CTAs), monotonic generation
__device__ __forceinline__ void dir_barrier(int dir, unsigned n) {
    __syncthreads();
    if (threadIdx.x == 0) {
        unsigned* cnt = &g_bar_count[dir];
        unsigned* gen = &g_bar_gen[dir];
        unsigned old;
        asm volatile("atom.acq_rel.gpu.global.add.u32 %0, [%1], 1;"
                     : "=r"(old) : "l"(cnt) : "memory");
        if (old == n * 64u - 1u) {
            asm volatile("red.release.gpu.global.add.u32 [%0], 1;" :: "l"(gen) : "memory");
        } else {
            unsigned cur;
            do {
                __nanosleep(32);
                asm volatile("ld.acquire.gpu.global.u32 %0, [%1];"
                             : "=r"(cur) : "l"(gen) : "memory");
            } while (cur < n);
        }
    }
    __syncthreads();
}

// ---------------- batched transpose for w_ih: in[3072][K] -> out[K][3072] ----------------
__global__ void transpose_ih(const float* f0, const float* b0,
                             const float* f1, const float* b1,
                             float* df0, float* db0, float* df1, float* db1) {
    __shared__ float tile[32][33];
    const float* in; float* out; int K;
    switch (blockIdx.z) {
        case 0: in = f0; out = df0; K = II; break;
        case 1: in = b0; out = db0; K = II; break;
        case 2: in = f1; out = df1; K = H2; break;
        default: in = b1; out = db1; K = H2; break;
    }
    int n0 = blockIdx.x * 32, k0 = blockIdx.y * 32;
    if (k0 >= K) return;
    for (int i = threadIdx.y; i < 32; i += 8)
        tile[i][threadIdx.x] = in[(size_t)(n0 + i) * K + k0 + threadIdx.x];
    __syncthreads();
    for (int i = threadIdx.y; i < 32; i += 8)
        out[(size_t)(k0 + i) * G3 + n0 + threadIdx.x] = tile[threadIdx.x][i];
}

// ---------------- prepack W_hh (coalesced reads, scattered writes) ----------------
// dst[jblk*49152 + kp*96 + g*32 + jp*4 + kk*2 + c] = src[(g*1024+jblk*16+jp*2+c)*HH + kp*2+kk]
__global__ void prepack_whh(const float* w00, const float* w01,
                            const float* w10, const float* w11) {
    int mat = blockIdx.y;
    const float* src = (mat == 0) ? w00 : (mat == 1) ? w01 : (mat == 2) ? w10 : w11;
    float* dst = g_whh_p[mat >> 1][mat & 1];
    int idx = blockIdx.x * 256 + threadIdx.x;   // 0 .. 3145727 (n*1024 + k)
    int k = idx & 1023;
    int n = idx >> 10;
    int g = n >> 10;
    int nj = n & 1023;
    int jblk = nj >> 4;
    int jp = (nj >> 1) & 7;
    int c  = nj & 1;
    int kp = k >> 1;
    int kk = k & 1;
    dst[jblk * 49152 + kp * 96 + g * 32 + jp * 4 + kk * 2 + c] = src[idx];
}

// ---------------- SGEMM 128x128x16, 8x8 per thread, f32x2 ----------------
// C[m][n] = sum_k Xrow(m)[k] * Wt[k][n] + bias[n];  m = s*BB + b
__global__ __launch_bounds__(256) void gemm_gx(
    const float* __restrict__ X, int strideB, int strideS, int K,
    const float* __restrict__ Wt, const float* __restrict__ bias,
    float* __restrict__ C)
{
    __shared__ float As[16][128];
    __shared__ float Bs[16][128];
    const int tid = threadIdx.x;
    const int bn = blockIdx.x * 128;
    const int bm = blockIdx.y * 128;
    const int tx = tid & 15, ty = tid >> 4;

    // A-load indices: 2 float4 per thread
    const int rowA0 = tid >> 2;            // 0..63
    const int rowA1 = rowA0 + 64;
    const int qa = tid & 3;
    int m0 = bm + rowA0, m1 = bm + rowA1;
    const float* Xr0 = X + (size_t)(m0 & 31) * strideB + (size_t)(m0 >> 5) * strideS;
    const float* Xr1 = X + (size_t)(m1 & 31) * strideB + (size_t)(m1 >> 5) * strideS;
    // B-load indices: 2 float4 per thread
    const int krB = tid >> 5;              // 0..7 ; second = +8
    const int nqB = tid & 31;

    float2 acc[8][4];
#pragma unroll
    for (int i = 0; i < 8; i++)
#pragma unroll
        for (int j = 0; j < 4; j++) acc[i][j] = make_float2(0.f, 0.f);

    for (int k0 = 0; k0 < K; k0 += 16) {
        float4 a0 = *(const float4*)(Xr0 + k0 + qa * 4);
        float4 a1 = *(const float4*)(Xr1 + k0 + qa * 4);
        float4 b0 = *(const float4*)(Wt + (size_t)(k0 + krB) * G3 + bn + nqB * 4);
        float4 b1 = *(const float4*)(Wt + (size_t)(k0 + krB + 8) * G3 + bn + nqB * 4);
        __syncthreads();
        As[qa * 4 + 0][rowA0] = a0.x;
        As[qa * 4 + 1][rowA0] = a0.y;
        As[qa * 4 + 2][rowA0] = a0.z;
        As[qa * 4 + 3][rowA0] = a0.w;
        As[qa * 4 + 0][rowA1] = a1.x;
        As[qa * 4 + 1][rowA1] = a1.y;
        As[qa * 4 + 2][rowA1] = a1.z;
        As[qa * 4 + 3][rowA1] = a1.w;
        *(float4*)&Bs[krB][nqB * 4] = b0;
        *(float4*)&Bs[krB + 8][nqB * 4] = b1;
        __syncthreads();
#pragma unroll
        for (int kk = 0; kk < 16; kk++) {
            float4 av0 = *(const float4*)&As[kk][ty * 8];
            float4 av1 = *(const float4*)&As[kk][ty * 8 + 4];
            float4 bv0 = *(const float4*)&Bs[kk][tx * 8];
            float4 bv1 = *(const float4*)&Bs[kk][tx * 8 + 4];
            float aa[8] = {av0.x, av0.y, av0.z, av0.w, av1.x, av1.y, av1.z, av1.w};
            float2 bb[4] = {make_float2(bv0.x, bv0.y), make_float2(bv0.z, bv0.w),
                            make_float2(bv1.x, bv1.y), make_float2(bv1.z, bv1.w)};
#pragma unroll
            for (int i = 0; i < 8; i++) {
                float2 a2 = make_float2(aa[i], aa[i]);
#pragma unroll
                for (int j = 0; j < 4; j++) acc[i][j] = ffma2(a2, bb[j], acc[i][j]);
            }
        }
    }

    float4 bsv0 = *(const float4*)(bias + bn + tx * 8);
    float4 bsv1 = *(const float4*)(bias + bn + tx * 8 + 4);
    float bv[8] = {bsv0.x, bsv0.y, bsv0.z, bsv0.w, bsv1.x, bsv1.y, bsv1.z, bsv1.w};
#pragma unroll
    for (int i = 0; i < 8; i++) {
        int m2 = bm + ty * 8 + i;
        float* crow = C + (size_t)m2 * G3 + bn + tx * 8;
        float4 v0 = make_float4(acc[i][0].x + bv[0], acc[i][0].y + bv[1],
                                acc[i][1].x + bv[2], acc[i][1].y + bv[3]);
        float4 v1 = make_float4(acc[i][2].x + bv[4], acc[i][2].y + bv[5],
                                acc[i][3].x + bv[6], acc[i][3].y + bv[7]);
        *(float4*)(crow) = v0;
        *(float4*)(crow + 4) = v1;
    }
}

// ---------------- persistent recurrent layer ----------------
// grid (64 jblks, 2 dirs), 512 thr: ks = tid>>8 (k-split), warp lanes = 8b x 4jp.
__global__ __launch_bounds__(512, 1) void gru_layer(
    int layer, const float* __restrict__ bhh_f, const float* __restrict__ bhh_b)
{
    extern __shared__ float smem[];
    float* wsm   = smem;                       // 49152 floats
    float* hbufs = smem + W_SM_FLOATS;         // 4 x 2176 floats

    const int dir  = blockIdx.y;
    const int jblk = blockIdx.x;
    const int tid  = threadIdx.x;
    const int ks   = tid >> 8;                 // 0/1 k-split group
    const int t8   = tid & 255;
    const int w8   = t8 >> 5;                  // warp-in-group 0..7
    const int lane = tid & 31;
    const int b    = (w8 >> 1) * 8 + (lane >> 2);
    const int jp   = (w8 & 1) * 4 + (lane & 3);
    const int j0   = jblk * 16 + jp * 2;
    const int koff0 = ks * 512;                // this group's k base

    // stage W slice once
    const float* wsrc = g_whh_p[layer][dir] + (size_t)jblk * W_SM_FLOATS;
    for (int i = tid; i < W_SM_FLOATS / 4; i += 512)
        *(float4*)&wsm[i * 4] = *(const float4*)&wsrc[i * 4];

    const float* bhh = dir ? bhh_b : bhh_f;
    const float2 br  = *(const float2*)(bhh + j0);
    const float2 bz  = *(const float2*)(bhh + HH + j0);
    const float2 bn2 = *(const float2*)(bhh + 2 * HH + j0);
    const float* gx_base = g_gx[dir];
    float* hb_base = hbufs + ks * 2 * HBUF_FLOATS;
    __syncthreads();

    for (int t = 0; t < SS; t++) {
        const float* hprev = g_h[dir][t & 1];
        const int s_sel = dir ? (SS - 1 - t) : t;

        float2 xr, xz, xn, hp;
        if (ks == 0) {
            const float* gxp = gx_base + ((size_t)s_sel * BB + b) * G3 + j0;
            xr = ldcg2(gxp);
            xz = ldcg2(gxp + HH);
            xn = ldcg2(gxp + 2 * HH);
            hp = ldcg2(hprev + b * HH + j0);
        }

        // prefetch chunk 0 of this group's k range
        const int row0 = t8 >> 4, col0 = t8 & 15;           // f = t8
        const int row1 = (t8 + 256) >> 4, col1 = t8 & 15;   // f = t8+256
        float4 hr0 = ldcg4(hprev + row0 * HH + koff0 + col0 * 4);
        float4 hr1 = ldcg4(hprev + row1 * HH + koff0 + col1 * 4);

        float2 accr = make_float2(0.f, 0.f), accz = accr, accn = accr;
        int buf = 0;
        for (int cc = 0; cc < 8; cc++) {
            float* hb = hb_base + buf * HBUF_FLOATS;
            *(float4*)&hb[row0 * HSTRIDE + col0 * 4] = hr0;
            *(float4*)&hb[row1 * HSTRIDE + col1 * 4] = hr1;
            __syncthreads();
            if (cc < 7) {
                int koff = koff0 + (cc + 1) * HCHUNK;
                hr0 = ldcg4(hprev + row0 * HH + koff + col0 * 4);
                hr1 = ldcg4(hprev + row1 * HH + koff + col1 * 4);
            }
            const float* hrow = hb + b * HSTRIDE;
            const int kpc = ks * 256 + cc * 32;
            const float* wq = wsm + (size_t)kpc * 96 + jp * 4;
#pragma unroll 8
            for (int kp4 = 0; kp4 < 16; kp4++) {
                float4 h4 = *(const float4*)&hrow[kp4 * 4];
                const float* w0 = wq + (kp4 * 2) * 96;
                float4 wr0 = *(const float4*)(w0);
                float4 wz0 = *(const float4*)(w0 + 32);
                float4 wn0 = *(const float4*)(w0 + 64);
                accr = ffma2(make_float2(h4.x, h4.x), make_float2(wr0.x, wr0.y), accr);
                accr = ffma2(make_float2(h4.y, h4.y), make_float2(wr0.z, wr0.w), accr);
                accz = ffma2(make_float2(h4.x, h4.x), make_float2(wz0.x, wz0.y), accz);
                accz = ffma2(make_float2(h4.y, h4.y), make_float2(wz0.z, wz0.w), accz);
                accn = ffma2(make_float2(h4.x, h4.x), make_float2(wn0.x, wn0.y), accn);
                accn = ffma2(make_float2(h4.y, h4.y), make_float2(wn0.z, wn0.w), accn);
                const float* w1 = w0 + 96;
                float4 wr1 = *(const float4*)(w1);
                float4 wz1 = *(const float4*)(w1 + 32);
                float4 wn1 = *(const float4*)(w1 + 64);
                accr = ffma2(make_float2(h4.z, h4.z), make_float2(wr1.x, wr1.y), accr);
                accr = ffma2(make_float2(h4.w, h4.w), make_float2(wr1.z, wr1.w), accr);
                accz = ffma2(make_float2(h4.z, h4.z), make_float2(wz1.x, wz1.y), accz);
                accz = ffma2(make_float2(h4.w, h4.w), make_float2(wz1.z, wz1.w), accz);
                accn = ffma2(make_float2(h4.z, h4.z), make_float2(wn1.x, wn1.y), accn);
                accn = ffma2(make_float2(h4.w, h4.w), make_float2(wn1.z, wn1.w), accn);
            }
            buf ^= 1;
        }

        // cross-group reduction + gates
        __syncthreads();
        float2* red = (float2*)hbufs;
        const int ri = (b * 8 + jp) * 3;
        if (ks == 1) {
            red[ri + 0] = accr;
            red[ri + 1] = accz;
            red[ri + 2] = accn;
        }
        __syncthreads();
        if (ks == 0) {
            float2 pr = red[ri + 0], pz = red[ri + 1], pn = red[ri + 2];
            accr.x += pr.x; accr.y += pr.y;
            accz.x += pz.x; accz.y += pz.y;
            accn.x += pn.x; accn.y += pn.y;

            float r0 = sigmoidf_(xr.x + accr.x + br.x);
            float r1 = sigmoidf_(xr.y + accr.y + br.y);
            float z0 = sigmoidf_(xz.x + accz.x + bz.x);
            float z1 = sigmoidf_(xz.y + accz.y + bz.y);
            float n0 = tanhf(xn.x + r0 * (accn.x + bn2.x));
            float n1 = tanhf(xn.y + r1 * (accn.y + bn2.y));
            float h0n = (1.f - z0) * n0 + z0 * hp.x;
            float h1n = (1.f - z1) * n1 + z1 * hp.y;

            float* hout = g_h[dir][(t + 1) & 1];
            *(float2*)(hout + b * HH + j0) = make_float2(h0n, h1n);
            if (layer == 0)
                *(float2*)(&g_out0[((size_t)b * SS + s_sel) * H2 + dir * HH + j0]) =
                    make_float2(h0n, h1n);
        }

        dir_barrier(dir, (unsigned)(t + 1));
    }
}

// ---------------- zero hidden + barrier state ----------------
__global__ void zero_h_k() {
    int i = blockIdx.x * blockDim.x + threadIdx.x;
    if (i < BB * HH) { g_h[0][0][i] = 0.f; g_h[1][0][i] = 0.f; }
    if (i < 2) { g_bar_count[i] = 0u; g_bar_gen[i] = 0u; }
}

// ---------------- final output ----------------
__global__ void finalize_k(float* __restrict__ out) {
    int i = blockIdx.x * blockDim.x + threadIdx.x;
    if (i < BB * H2) {
        int b = i >> 11, c = i & 2047;
        out[i] = (c < HH) ? g_h[0][0][b * HH + c] : g_h[1][0][b * HH + c - HH];
    }
}

// ---------------- host ----------------
extern "C" void kernel_launch(void* const* d_in, const int* in_sizes, int n_in,
                              void* d_out, int out_size)
{
    const float* x       = (const float*)d_in[0];
    const float* w_ih_f0 = (const float*)d_in[1];
    const float* w_hh_f0 = (const float*)d_in[2];
    const float* b_ih_f0 = (const float*)d_in[3];
    const float* b_hh_f0 = (const float*)d_in[4];
    const float* w_ih_b0 = (const float*)d_in[5];
    const float* w_hh_b0 = (const float*)d_in[6];
    const float* b_ih_b0 = (const float*)d_in[7];
    const float* b_hh_b0 = (const float*)d_in[8];
    const float* w_ih_f1 = (const float*)d_in[9];
    const float* w_hh_f1 = (const float*)d_in[10];
    const float* b_ih_f1 = (const float*)d_in[11];
    const float* b_hh_f1 = (const float*)d_in[12];
    const float* w_ih_b1 = (const float*)d_in[13];
    const float* w_hh_b1 = (const float*)d_in[14];
    const float* b_ih_b1 = (const float*)d_in[15];
    const float* b_hh_b1 = (const float*)d_in[16];
    float* out = (float*)d_out;

    size_t gru_smem = GRU_SMEM_FLOATS * sizeof(float);
    cudaFuncSetAttribute(gru_layer, cudaFuncAttributeMaxDynamicSharedMemorySize,
                         (int)gru_smem);

    float *wih0, *wih1, *gx, *out0;
    cudaGetSymbolAddress((void**)&wih0, g_wih0_t);
    cudaGetSymbolAddress((void**)&wih1, g_wih1_t);
    cudaGetSymbolAddress((void**)&gx,   g_gx);
    cudaGetSymbolAddress((void**)&out0, g_out0);

    float* wih0_f = wih0;
    float* wih0_b = wih0 + (size_t)II * G3;
    float* wih1_f = wih1;
    float* wih1_b = wih1 + (size_t)H2 * G3;
    float* gx_f = gx;
    float* gx_b = gx + (size_t)BB * SS * G3;

    dim3 ggrid(G3 / 128, (BB * SS) / 128);

    // 1
    transpose_ih<<<dim3(96, 64, 4), dim3(32, 8)>>>(
        w_ih_f0, w_ih_b0, w_ih_f1, w_ih_b1, wih0_f, wih0_b, wih1_f, wih1_b);
    // 2, 3: layer0 gx GEMMs
    gemm_gx<<<ggrid, 256>>>(x, SS * II, II, II, wih0_f, b_ih_f0, gx_f);
    gemm_gx<<<ggrid, 256>>>(x, SS * II, II, II, wih0_b, b_ih_b0, gx_b);
    // 4
    prepack_whh<<<dim3(12288, 4), 256>>>(w_hh_f0, w_hh_b0, w_hh_f1, w_hh_b1);
    // 5
    zero_h_k<<<(BB * HH + 255) / 256, 256>>>();
    // 6: layer0 recurrence
    gru_layer<<<dim3(64, 2), 512, gru_smem>>>(0, b_hh_f0, b_hh_b0);

    // layer 1
    gemm_gx<<<ggrid, 256>>>(out0, SS * H2, H2, H2, wih1_f, b_ih_f1, gx_f);
    gemm_gx<<<ggrid, 256>>>(out0, SS * H2, H2, H2, wih1_b, b_ih_b1, gx_b);
    zero_h_k<<<(BB * HH + 255) / 256, 256>>>();
    gru_layer<<<dim3(64, 2), 512, gru_smem>>>(1, b_hh_f1, b_hh_b1);

    finalize_k<<<(BB * H2 + 255) / 256, 256>>>(out);
}

// round 5
// speedup vs baseline: 1.9791x; 1.0048x over previous
#include <cuda_runtime.h>
#include <math.h>

#define BB 32
#define SS 512
#define II 512
#define HH 1024
#define G3 3072
#define H2 2048

#define W_SM_FLOATS (512 * 96)        // per-CTA W slice (196,608 B)
#define HCHUNK 64                     // k per staged chunk
#define HSTRIDE 68                    // 64 + 4 pad
#define HBUF_FLOATS (32 * HSTRIDE)    // 2176 floats per buffer
#define GRU_SMEM_FLOATS (W_SM_FLOATS + 4 * HBUF_FLOATS)   // 231,424 B

// ---------------- device scratch ----------------
__device__ float g_wih0_t[2][II * G3];
__device__ float g_wih1_t[2][(size_t)H2 * G3];
__device__ float g_whh_p[2][2][HH * G3];
__device__ float g_gx[2][(size_t)BB * SS * G3];
__device__ float g_h[2][2][BB * HH];
__device__ float g_out0[(size_t)BB * SS * H2];
__device__ unsigned g_bar_count[2];
__device__ unsigned g_bar_gen[2];

// ---------------- helpers ----------------
__device__ __forceinline__ float2 ffma2(float2 a, float2 b, float2 c) {
    unsigned long long A = *reinterpret_cast<unsigned long long*>(&a);
    unsigned long long B = *reinterpret_cast<unsigned long long*>(&b);
    unsigned long long C = *reinterpret_cast<unsigned long long*>(&c);
    unsigned long long D;
    asm("fma.rn.f32x2 %0, %1, %2, %3;" : "=l"(D) : "l"(A), "l"(B), "l"(C));
    return *reinterpret_cast<float2*>(&D);
}

__device__ __forceinline__ float sigmoidf_(float x) { return 1.0f / (1.0f + expf(-x)); }

__device__ __forceinline__ float4 ldcg4(const float* p) {
    float4 v;
    asm volatile("ld.global.cg.v4.f32 {%0,%1,%2,%3}, [%4];"
                 : "=f"(v.x), "=f"(v.y), "=f"(v.z), "=f"(v.w) : "l"(p));
    return v;
}
__device__ __forceinline__ float2 ldcg2(const float* p) {
    float2 v;
    asm volatile("ld.global.cg.v2.f32 {%0,%1}, [%2];" : "=f"(v.x), "=f"(v.y) : "l"(p));
    return v;
}

// grid barrier per direction (64 CTAs), monotonic generation
__device__ __forceinline__ void dir_barrier(int dir, unsigned n) {
    __syncthreads();
    if (threadIdx.x == 0) {
        unsigned* cnt = &g_bar_count[dir];
        unsigned* gen = &g_bar_gen[dir];
        unsigned old;
        asm volatile("atom.acq_rel.gpu.global.add.u32 %0, [%1], 1;"
                     : "=r"(old) : "l"(cnt) : "memory");
        if (old == n * 64u - 1u) {
            asm volatile("red.release.gpu.global.add.u32 [%0], 1;" :: "l"(gen) : "memory");
        } else {
            unsigned cur;
            do {
                __nanosleep(16);
                asm volatile("ld.acquire.gpu.global.u32 %0, [%1];"
                             : "=r"(cur) : "l"(gen) : "memory");
            } while (cur < n);
        }
    }
    __syncthreads();
}

// ---------------- batched transpose for w_ih: in[3072][K] -> out[K][3072] ----------------
__global__ void transpose_ih(const float* f0, const float* b0,
                             const float* f1, const float* b1,
                             float* df0, float* db0, float* df1, float* db1) {
    __shared__ float tile[32][33];
    const float* in; float* out; int K;
    switch (blockIdx.z) {
        case 0: in = f0; out = df0; K = II; break;
        case 1: in = b0; out = db0; K = II; break;
        case 2: in = f1; out = df1; K = H2; break;
        default: in = b1; out = db1; K = H2; break;
    }
    int n0 = blockIdx.x * 32, k0 = blockIdx.y * 32;
    if (k0 >= K) return;
    for (int i = threadIdx.y; i < 32; i += 8)
        tile[i][threadIdx.x] = in[(size_t)(n0 + i) * K + k0 + threadIdx.x];
    __syncthreads();
    for (int i = threadIdx.y; i < 32; i += 8)
        out[(size_t)(k0 + i) * G3 + n0 + threadIdx.x] = tile[threadIdx.x][i];
}

// ---------------- prepack W_hh + zero h / barrier state ----------------
__global__ void prepack_whh(const float* w00, const float* w01,
                            const float* w10, const float* w11) {
    int mat = blockIdx.y;
    const float* src = (mat == 0) ? w00 : (mat == 1) ? w01 : (mat == 2) ? w10 : w11;
    float* dst = g_whh_p[mat >> 1][mat & 1];
    int idx = blockIdx.x * 256 + threadIdx.x;   // 0 .. 3145727 (n*1024 + k)
    int k = idx & 1023;
    int n = idx >> 10;
    int g = n >> 10;
    int nj = n & 1023;
    int jblk = nj >> 4;
    int jp = (nj >> 1) & 7;
    int c  = nj & 1;
    int kp = k >> 1;
    int kk = k & 1;
    dst[jblk * 49152 + kp * 96 + g * 32 + jp * 4 + kk * 2 + c] = src[idx];
    if (mat == 0) {
        if (idx < BB * HH) { g_h[0][0][idx] = 0.f; g_h[1][0][idx] = 0.f; }
        if (idx < 2) { g_bar_count[idx] = 0u; g_bar_gen[idx] = 0u; }
    }
}

// ---------------- SGEMM 128x128x16, both directions via blockIdx.z ----------------
__global__ __launch_bounds__(256) void gemm_gx2(
    const float* __restrict__ X, int strideB, int strideS, int K,
    const float* __restrict__ Wt0, const float* __restrict__ Wt1,
    const float* __restrict__ bias0, const float* __restrict__ bias1,
    float* __restrict__ C0, float* __restrict__ C1)
{
    __shared__ float As[16][128];
    __shared__ float Bs[16][128];
    const float* Wt   = blockIdx.z ? Wt1 : Wt0;
    const float* bias = blockIdx.z ? bias1 : bias0;
    float* C          = blockIdx.z ? C1 : C0;

    const int tid = threadIdx.x;
    const int bn = blockIdx.x * 128;
    const int bm = blockIdx.y * 128;
    const int tx = tid & 15, ty = tid >> 4;

    const int rowA0 = tid >> 2;
    const int rowA1 = rowA0 + 64;
    const int qa = tid & 3;
    int m0 = bm + rowA0, m1 = bm + rowA1;
    const float* Xr0 = X + (size_t)(m0 & 31) * strideB + (size_t)(m0 >> 5) * strideS;
    const float* Xr1 = X + (size_t)(m1 & 31) * strideB + (size_t)(m1 >> 5) * strideS;
    const int krB = tid >> 5;
    const int nqB = tid & 31;

    float2 acc[8][4];
#pragma unroll
    for (int i = 0; i < 8; i++)
#pragma unroll
        for (int j = 0; j < 4; j++) acc[i][j] = make_float2(0.f, 0.f);

    for (int k0 = 0; k0 < K; k0 += 16) {
        float4 a0 = *(const float4*)(Xr0 + k0 + qa * 4);
        float4 a1 = *(const float4*)(Xr1 + k0 + qa * 4);
        float4 b0 = *(const float4*)(Wt + (size_t)(k0 + krB) * G3 + bn + nqB * 4);
        float4 b1 = *(const float4*)(Wt + (size_t)(k0 + krB + 8) * G3 + bn + nqB * 4);
        __syncthreads();
        As[qa * 4 + 0][rowA0] = a0.x;
        As[qa * 4 + 1][rowA0] = a0.y;
        As[qa * 4 + 2][rowA0] = a0.z;
        As[qa * 4 + 3][rowA0] = a0.w;
        As[qa * 4 + 0][rowA1] = a1.x;
        As[qa * 4 + 1][rowA1] = a1.y;
        As[qa * 4 + 2][rowA1] = a1.z;
        As[qa * 4 + 3][rowA1] = a1.w;
        *(float4*)&Bs[krB][nqB * 4] = b0;
        *(float4*)&Bs[krB + 8][nqB * 4] = b1;
        __syncthreads();
#pragma unroll
        for (int kk = 0; kk < 16; kk++) {
            float4 av0 = *(const float4*)&As[kk][ty * 8];
            float4 av1 = *(const float4*)&As[kk][ty * 8 + 4];
            float4 bv0 = *(const float4*)&Bs[kk][tx * 8];
            float4 bv1 = *(const float4*)&Bs[kk][tx * 8 + 4];
            float aa[8] = {av0.x, av0.y, av0.z, av0.w, av1.x, av1.y, av1.z, av1.w};
            float2 bb[4] = {make_float2(bv0.x, bv0.y), make_float2(bv0.z, bv0.w),
                            make_float2(bv1.x, bv1.y), make_float2(bv1.z, bv1.w)};
#pragma unroll
            for (int i = 0; i < 8; i++) {
                float2 a2 = make_float2(aa[i], aa[i]);
#pragma unroll
                for (int j = 0; j < 4; j++) acc[i][j] = ffma2(a2, bb[j], acc[i][j]);
            }
        }
    }

    float4 bsv0 = *(const float4*)(bias + bn + tx * 8);
    float4 bsv1 = *(const float4*)(bias + bn + tx * 8 + 4);
    float bv[8] = {bsv0.x, bsv0.y, bsv0.z, bsv0.w, bsv1.x, bsv1.y, bsv1.z, bsv1.w};
#pragma unroll
    for (int i = 0; i < 8; i++) {
        int m2 = bm + ty * 8 + i;
        float* crow = C + (size_t)m2 * G3 + bn + tx * 8;
        float4 v0 = make_float4(acc[i][0].x + bv[0], acc[i][0].y + bv[1],
                                acc[i][1].x + bv[2], acc[i][1].y + bv[3]);
        float4 v1 = make_float4(acc[i][2].x + bv[4], acc[i][2].y + bv[5],
                                acc[i][3].x + bv[6], acc[i][3].y + bv[7]);
        *(float4*)(crow) = v0;
        *(float4*)(crow + 4) = v1;
    }
}

// ---------------- persistent recurrent layer ----------------
// grid (64 jblks, 2 dirs), 512 thr: ks = tid>>8 (k-split), warp lanes = 8b x 4jp.
__global__ __launch_bounds__(512, 1) void gru_layer(
    int layer, const float* __restrict__ bhh_f, const float* __restrict__ bhh_b)
{
    extern __shared__ float smem[];
    float* wsm   = smem;                       // 49152 floats
    float* hbufs = smem + W_SM_FLOATS;         // 4 x 2176 floats

    const int dir  = blockIdx.y;
    const int jblk = blockIdx.x;
    const int tid  = threadIdx.x;
    const int ks   = tid >> 8;
    const int t8   = tid & 255;
    const int w8   = t8 >> 5;
    const int lane = tid & 31;
    const int b    = (w8 >> 1) * 8 + (lane >> 2);
    const int jp   = (w8 & 1) * 4 + (lane & 3);
    const int j0   = jblk * 16 + jp * 2;
    const int koff0 = ks * 512;

    const float* wsrc = g_whh_p[layer][dir] + (size_t)jblk * W_SM_FLOATS;
    for (int i = tid; i < W_SM_FLOATS / 4; i += 512)
        *(float4*)&wsm[i * 4] = *(const float4*)&wsrc[i * 4];

    const float* bhh = dir ? bhh_b : bhh_f;
    const float2 br  = *(const float2*)(bhh + j0);
    const float2 bz  = *(const float2*)(bhh + HH + j0);
    const float2 bn2 = *(const float2*)(bhh + 2 * HH + j0);
    const float* gx_base = g_gx[dir];
    float* hb_base = hbufs + ks * 2 * HBUF_FLOATS;
    __syncthreads();

    for (int t = 0; t < SS; t++) {
        const float* hprev = g_h[dir][t & 1];
        const int s_sel = dir ? (SS - 1 - t) : t;

        float2 xr, xz, xn, hp;
        if (ks == 0) {
            const float* gxp = gx_base + ((size_t)s_sel * BB + b) * G3 + j0;
            xr = ldcg2(gxp);
            xz = ldcg2(gxp + HH);
            xn = ldcg2(gxp + 2 * HH);
            hp = ldcg2(hprev + b * HH + j0);
        }

        const int row0 = t8 >> 4, col0 = t8 & 15;
        const int row1 = (t8 + 256) >> 4, col1 = t8 & 15;
        float4 hr0 = ldcg4(hprev + row0 * HH + koff0 + col0 * 4);
        float4 hr1 = ldcg4(hprev + row1 * HH + koff0 + col1 * 4);

        float2 accr = make_float2(0.f, 0.f), accz = accr, accn = accr;
        int buf = 0;
        for (int cc = 0; cc < 8; cc++) {
            float* hb = hb_base + buf * HBUF_FLOATS;
            *(float4*)&hb[row0 * HSTRIDE + col0 * 4] = hr0;
            *(float4*)&hb[row1 * HSTRIDE + col1 * 4] = hr1;
            __syncthreads();
            if (cc < 7) {
                int koff = koff0 + (cc + 1) * HCHUNK;
                hr0 = ldcg4(hprev + row0 * HH + koff + col0 * 4);
                hr1 = ldcg4(hprev + row1 * HH + koff + col1 * 4);
            }
            const float* hrow = hb + b * HSTRIDE;
            const int kpc = ks * 256 + cc * 32;
            const float* wq = wsm + (size_t)kpc * 96 + jp * 4;
#pragma unroll 2
            for (int kp4 = 0; kp4 < 16; kp4++) {
                float4 h4 = *(const float4*)&hrow[kp4 * 4];
                const float* w0 = wq + (kp4 * 2) * 96;
                float4 wr0 = *(const float4*)(w0);
                float4 wz0 = *(const float4*)(w0 + 32);
                float4 wn0 = *(const float4*)(w0 + 64);
                accr = ffma2(make_float2(h4.x, h4.x), make_float2(wr0.x, wr0.y), accr);
                accz = ffma2(make_float2(h4.x, h4.x), make_float2(wz0.x, wz0.y), accz);
                accn = ffma2(make_float2(h4.x, h4.x), make_float2(wn0.x, wn0.y), accn);
                accr = ffma2(make_float2(h4.y, h4.y), make_float2(wr0.z, wr0.w), accr);
                accz = ffma2(make_float2(h4.y, h4.y), make_float2(wz0.z, wz0.w), accz);
                accn = ffma2(make_float2(h4.y, h4.y), make_float2(wn0.z, wn0.w), accn);
                const float* w1 = w0 + 96;
                float4 wr1 = *(const float4*)(w1);
                float4 wz1 = *(const float4*)(w1 + 32);
                float4 wn1 = *(const float4*)(w1 + 64);
                accr = ffma2(make_float2(h4.z, h4.z), make_float2(wr1.x, wr1.y), accr);
                accz = ffma2(make_float2(h4.z, h4.z), make_float2(wz1.x, wz1.y), accz);
                accn = ffma2(make_float2(h4.z, h4.z), make_float2(wn1.x, wn1.y), accn);
                accr = ffma2(make_float2(h4.w, h4.w), make_float2(wr1.z, wr1.w), accr);
                accz = ffma2(make_float2(h4.w, h4.w), make_float2(wz1.z, wz1.w), accz);
                accn = ffma2(make_float2(h4.w, h4.w), make_float2(wn1.z, wn1.w), accn);
            }
            buf ^= 1;
        }

        __syncthreads();
        float2* red = (float2*)hbufs;
        const int ri = (b * 8 + jp) * 3;
        if (ks == 1) {
            red[ri + 0] = accr;
            red[ri + 1] = accz;
            red[ri + 2] = accn;
        }
        __syncthreads();
        if (ks == 0) {
            float2 pr = red[ri + 0], pz = red[ri + 1], pn = red[ri + 2];
            accr.x += pr.x; accr.y += pr.y;
            accz.x += pz.x; accz.y += pz.y;
            accn.x += pn.x; accn.y += pn.y;

            float r0 = sigmoidf_(xr.x + accr.x + br.x);
            float r1 = sigmoidf_(xr.y + accr.y + br.y);
            float z0 = sigmoidf_(xz.x + accz.x + bz.x);
            float z1 = sigmoidf_(xz.y + accz.y + bz.y);
            float n0 = tanhf(xn.x + r0 * (accn.x + bn2.x));
            float n1 = tanhf(xn.y + r1 * (accn.y + bn2.y));
            float h0n = (1.f - z0) * n0 + z0 * hp.x;
            float h1n = (1.f - z1) * n1 + z1 * hp.y;

            float* hout = g_h[dir][(t + 1) & 1];
            *(float2*)(hout + b * HH + j0) = make_float2(h0n, h1n);
            if (layer == 0)
                *(float2*)(&g_out0[((size_t)b * SS + s_sel) * H2 + dir * HH + j0]) =
                    make_float2(h0n, h1n);
        }

        dir_barrier(dir, (unsigned)(t + 1));
    }
}

// ---------------- zero hidden + barrier state (between layers) ----------------
__global__ void zero_h_k() {
    int i = blockIdx.x * blockDim.x + threadIdx.x;
    if (i < BB * HH) { g_h[0][0][i] = 0.f; g_h[1][0][i] = 0.f; }
    if (i < 2) { g_bar_count[i] = 0u; g_bar_gen[i] = 0u; }
}

// ---------------- final output ----------------
__global__ void finalize_k(float* __restrict__ out) {
    int i = blockIdx.x * blockDim.x + threadIdx.x;
    if (i < BB * H2) {
        int b = i >> 11, c = i & 2047;
        out[i] = (c < HH) ? g_h[0][0][b * HH + c] : g_h[1][0][b * HH + c - HH];
    }
}

// ---------------- host ----------------
extern "C" void kernel_launch(void* const* d_in, const int* in_sizes, int n_in,
                              void* d_out, int out_size)
{
    const float* x       = (const float*)d_in[0];
    const float* w_ih_f0 = (const float*)d_in[1];
    const float* w_hh_f0 = (const float*)d_in[2];
    const float* b_ih_f0 = (const float*)d_in[3];
    const float* b_hh_f0 = (const float*)d_in[4];
    const float* w_ih_b0 = (const float*)d_in[5];
    const float* w_hh_b0 = (const float*)d_in[6];
    const float* b_ih_b0 = (const float*)d_in[7];
    const float* b_hh_b0 = (const float*)d_in[8];
    const float* w_ih_f1 = (const float*)d_in[9];
    const float* w_hh_f1 = (const float*)d_in[10];
    const float* b_ih_f1 = (const float*)d_in[11];
    const float* b_hh_f1 = (const float*)d_in[12];
    const float* w_ih_b1 = (const float*)d_in[13];
    const float* w_hh_b1 = (const float*)d_in[14];
    const float* b_ih_b1 = (const float*)d_in[15];
    const float* b_hh_b1 = (const float*)d_in[16];
    float* out = (float*)d_out;

    size_t gru_smem = GRU_SMEM_FLOATS * sizeof(float);
    cudaFuncSetAttribute(gru_layer, cudaFuncAttributeMaxDynamicSharedMemorySize,
                         (int)gru_smem);

    float *wih0, *wih1, *gx, *out0;
    cudaGetSymbolAddress((void**)&wih0, g_wih0_t);
    cudaGetSymbolAddress((void**)&wih1, g_wih1_t);
    cudaGetSymbolAddress((void**)&gx,   g_gx);
    cudaGetSymbolAddress((void**)&out0, g_out0);

    float* wih0_f = wih0;
    float* wih0_b = wih0 + (size_t)II * G3;
    float* wih1_f = wih1;
    float* wih1_b = wih1 + (size_t)H2 * G3;
    float* gx_f = gx;
    float* gx_b = gx + (size_t)BB * SS * G3;

    dim3 ggrid(G3 / 128, (BB * SS) / 128, 2);

    // #1
    transpose_ih<<<dim3(96, 64, 4), dim3(32, 8)>>>(
        w_ih_f0, w_ih_b0, w_ih_f1, w_ih_b1, wih0_f, wih0_b, wih1_f, wih1_b);
    // #2 (also zeroes h + barrier state)
    prepack_whh<<<dim3(12288, 4), 256>>>(w_hh_f0, w_hh_b0, w_hh_f1, w_hh_b1);
    // #3: layer0 gx for both dirs
    gemm_gx2<<<ggrid, 256>>>(x, SS * II, II, II, wih0_f, wih0_b,
                             b_ih_f0, b_ih_b0, gx_f, gx_b);
    // #4: layer0 recurrence (profiled slot)
    gru_layer<<<dim3(64, 2), 512, gru_smem>>>(0, b_hh_f0, b_hh_b0);

    // layer 1
    gemm_gx2<<<ggrid, 256>>>(out0, SS * H2, H2, H2, wih1_f, wih1_b,
                             b_ih_f1, b_ih_b1, gx_f, gx_b);
    zero_h_k<<<(BB * HH + 255) / 256, 256>>>();
    gru_layer<<<dim3(64, 2), 512, gru_smem>>>(1, b_hh_f1, b_hh_b1);

    finalize_k<<<(BB * H2 + 255) / 256, 256>>>(out);
}

// round 6
// speedup vs baseline: 3.1823x; 1.6080x over previous
#include <cuda_runtime.h>
#include <math.h>

#define BB 32
#define SS 512
#define II 512
#define HH 1024
#define G3 3072
#define H2 2048

#define W_SM_FLOATS (1024 * 48)       // per-CTA W slice: [k][3g][8jp] float2 = 196,608 B
#define RED_FLOAT2 (4 * 12 * 64)      // reduction buffer: 4 slots x 12 x 64 float2 = 24,576 B
#define GRU_SMEM_BYTES (W_SM_FLOATS * 4 + RED_FLOAT2 * 8)   // 221,184 B

// ---------------- device scratch ----------------
__device__ float g_wih0_t[2][II * G3];
__device__ float g_wih1_t[2][(size_t)H2 * G3];
__device__ float g_whh_p[2][2][HH * G3];
__device__ float g_gx[2][(size_t)BB * SS * G3];
__device__ float g_h[2][2][HH * BB];            // [dir][parity][j][b]  (j-major!)
__device__ float g_out0[(size_t)BB * SS * H2];
__device__ unsigned g_bar_count[2];
__device__ unsigned g_bar_gen[2];

// ---------------- helpers ----------------
__device__ __forceinline__ float2 ffma2(float2 a, float2 b, float2 c) {
    unsigned long long A = *reinterpret_cast<unsigned long long*>(&a);
    unsigned long long B = *reinterpret_cast<unsigned long long*>(&b);
    unsigned long long C = *reinterpret_cast<unsigned long long*>(&c);
    unsigned long long D;
    asm("fma.rn.f32x2 %0, %1, %2, %3;" : "=l"(D) : "l"(A), "l"(B), "l"(C));
    return *reinterpret_cast<float2*>(&D);
}
__device__ __forceinline__ float2 bcast2(float x) { return make_float2(x, x); }
__device__ __forceinline__ float sigmoidf_(float x) { return 1.0f / (1.0f + expf(-x)); }

__device__ __forceinline__ float4 ldcg4(const float* p) {
    float4 v;
    asm volatile("ld.global.cg.v4.f32 {%0,%1,%2,%3}, [%4];"
                 : "=f"(v.x), "=f"(v.y), "=f"(v.z), "=f"(v.w) : "l"(p));
    return v;
}
__device__ __forceinline__ float2 ldcg2(const float* p) {
    float2 v;
    asm volatile("ld.global.cg.v2.f32 {%0,%1}, [%2];" : "=f"(v.x), "=f"(v.y) : "l"(p));
    return v;
}

// grid barrier per direction (64 CTAs), monotonic generation
__device__ __forceinline__ void dir_barrier(int dir, unsigned n) {
    __syncthreads();
    if (threadIdx.x == 0) {
        unsigned* cnt = &g_bar_count[dir];
        unsigned* gen = &g_bar_gen[dir];
        unsigned old;
        asm volatile("atom.acq_rel.gpu.global.add.u32 %0, [%1], 1;"
                     : "=r"(old) : "l"(cnt) : "memory");
        if (old == n * 64u - 1u) {
            asm volatile("red.release.gpu.global.add.u32 [%0], 1;" :: "l"(gen) : "memory");
        } else {
            unsigned cur;
            do {
                __nanosleep(16);
                asm volatile("ld.acquire.gpu.global.u32 %0, [%1];"
                             : "=r"(cur) : "l"(gen) : "memory");
            } while (cur < n);
        }
    }
    __syncthreads();
}

// ---------------- batched transpose for w_ih: in[3072][K] -> out[K][3072] ----------------
__global__ void transpose_ih(const float* f0, const float* b0,
                             const float* f1, const float* b1,
                             float* df0, float* db0, float* df1, float* db1) {
    __shared__ float tile[32][33];
    const float* in; float* out; int K;
    switch (blockIdx.z) {
        case 0: in = f0; out = df0; K = II; break;
        case 1: in = b0; out = db0; K = II; break;
        case 2: in = f1; out = df1; K = H2; break;
        default: in = b1; out = db1; K = H2; break;
    }
    int n0 = blockIdx.x * 32, k0 = blockIdx.y * 32;
    if (k0 >= K) return;
    for (int i = threadIdx.y; i < 32; i += 8)
        tile[i][threadIdx.x] = in[(size_t)(n0 + i) * K + k0 + threadIdx.x];
    __syncthreads();
    for (int i = threadIdx.y; i < 32; i += 8)
        out[(size_t)(k0 + i) * G3 + n0 + threadIdx.x] = tile[threadIdx.x][i];
}

// ---------------- prepack W_hh into [jblk][k][g][jp][c] + zero h / barriers ----------------
__global__ void prepack_whh(const float* w00, const float* w01,
                            const float* w10, const float* w11) {
    int mat = blockIdx.y;
    const float* src = (mat == 0) ? w00 : (mat == 1) ? w01 : (mat == 2) ? w10 : w11;
    float* dst = g_whh_p[mat >> 1][mat & 1];
    int idx = blockIdx.x * 256 + threadIdx.x;   // n*1024 + k
    int k = idx & 1023;
    int n = idx >> 10;
    int g = n >> 10;
    int nj = n & 1023;
    int jblk = nj >> 4;
    int jp = (nj >> 1) & 7;
    int c  = nj & 1;
    dst[jblk * W_SM_FLOATS + k * 48 + g * 16 + jp * 2 + c] = src[idx];
    if (mat == 0) {
        if (idx < HH * BB) { g_h[0][0][idx] = 0.f; g_h[1][0][idx] = 0.f; }
        if (idx < 2) { g_bar_count[idx] = 0u; g_bar_gen[idx] = 0u; }
    }
}

// ---------------- SGEMM 128x128x16, both directions via blockIdx.z ----------------
__global__ __launch_bounds__(256) void gemm_gx2(
    const float* __restrict__ X, int strideB, int strideS, int K,
    const float* __restrict__ Wt0, const float* __restrict__ Wt1,
    const float* __restrict__ bias0, const float* __restrict__ bias1,
    float* __restrict__ C0, float* __restrict__ C1)
{
    __shared__ float As[16][128];
    __shared__ float Bs[16][128];
    const float* Wt   = blockIdx.z ? Wt1 : Wt0;
    const float* bias = blockIdx.z ? bias1 : bias0;
    float* C          = blockIdx.z ? C1 : C0;

    const int tid = threadIdx.x;
    const int bn = blockIdx.x * 128;
    const int bm = blockIdx.y * 128;
    const int tx = tid & 15, ty = tid >> 4;

    const int rowA0 = tid >> 2;
    const int rowA1 = rowA0 + 64;
    const int qa = tid & 3;
    int m0 = bm + rowA0, m1 = bm + rowA1;
    const float* Xr0 = X + (size_t)(m0 & 31) * strideB + (size_t)(m0 >> 5) * strideS;
    const float* Xr1 = X + (size_t)(m1 & 31) * strideB + (size_t)(m1 >> 5) * strideS;
    const int krB = tid >> 5;
    const int nqB = tid & 31;

    float2 acc[8][4];
#pragma unroll
    for (int i = 0; i < 8; i++)
#pragma unroll
        for (int j = 0; j < 4; j++) acc[i][j] = make_float2(0.f, 0.f);

    for (int k0 = 0; k0 < K; k0 += 16) {
        float4 a0 = *(const float4*)(Xr0 + k0 + qa * 4);
        float4 a1 = *(const float4*)(Xr1 + k0 + qa * 4);
        float4 b0 = *(const float4*)(Wt + (size_t)(k0 + krB) * G3 + bn + nqB * 4);
        float4 b1 = *(const float4*)(Wt + (size_t)(k0 + krB + 8) * G3 + bn + nqB * 4);
        __syncthreads();
        As[qa * 4 + 0][rowA0] = a0.x;
        As[qa * 4 + 1][rowA0] = a0.y;
        As[qa * 4 + 2][rowA0] = a0.z;
        As[qa * 4 + 3][rowA0] = a0.w;
        As[qa * 4 + 0][rowA1] = a1.x;
        As[qa * 4 + 1][rowA1] = a1.y;
        As[qa * 4 + 2][rowA1] = a1.z;
        As[qa * 4 + 3][rowA1] = a1.w;
        *(float4*)&Bs[krB][nqB * 4] = b0;
        *(float4*)&Bs[krB + 8][nqB * 4] = b1;
        __syncthreads();
#pragma unroll
        for (int kk = 0; kk < 16; kk++) {
            float4 av0 = *(const float4*)&As[kk][ty * 8];
            float4 av1 = *(const float4*)&As[kk][ty * 8 + 4];
            float4 bv0 = *(const float4*)&Bs[kk][tx * 8];
            float4 bv1 = *(const float4*)&Bs[kk][tx * 8 + 4];
            float aa[8] = {av0.x, av0.y, av0.z, av0.w, av1.x, av1.y, av1.z, av1.w};
            float2 bb[4] = {make_float2(bv0.x, bv0.y), make_float2(bv0.z, bv0.w),
                            make_float2(bv1.x, bv1.y), make_float2(bv1.z, bv1.w)};
#pragma unroll
            for (int i = 0; i < 8; i++) {
                float2 a2 = make_float2(aa[i], aa[i]);
#pragma unroll
                for (int j = 0; j < 4; j++) acc[i][j] = ffma2(a2, bb[j], acc[i][j]);
            }
        }
    }

    float4 bsv0 = *(const float4*)(bias + bn + tx * 8);
    float4 bsv1 = *(const float4*)(bias + bn + tx * 8 + 4);
    float bv[8] = {bsv0.x, bsv0.y, bsv0.z, bsv0.w, bsv1.x, bsv1.y, bsv1.z, bsv1.w};
#pragma unroll
    for (int i = 0; i < 8; i++) {
        int m2 = bm + ty * 8 + i;
        float* crow = C + (size_t)m2 * G3 + bn + tx * 8;
        float4 v0 = make_float4(acc[i][0].x + bv[0], acc[i][0].y + bv[1],
                                acc[i][1].x + bv[2], acc[i][1].y + bv[3]);
        float4 v1 = make_float4(acc[i][2].x + bv[4], acc[i][2].y + bv[5],
                                acc[i][3].x + bv[6], acc[i][3].y + bv[7]);
        *(float4*)(crow) = v0;
        *(float4*)(crow + 4) = v1;
    }
}

// ---------------- persistent recurrent layer (batch-blocked, k-split 8) ----------------
// grid (64 jblks, 2 dirs), 512 thr: tid = kg*64 + bg*8 + jp.
// Each thread: 4 b (bg*4..+3) x 2 j (jp*2..+1) x 3 gates over 128 k.
__global__ __launch_bounds__(512, 1) void gru_layer(
    int layer, const float* __restrict__ bhh_f, const float* __restrict__ bhh_b)
{
    extern __shared__ float smem[];
    float* wsm  = smem;                                   // 49152 floats
    float2* red = (float2*)(smem + W_SM_FLOATS);          // 3072 float2

    const int dir  = blockIdx.y;
    const int jblk = blockIdx.x;
    const int tid  = threadIdx.x;
    const int kg   = tid >> 6;          // 0..7
    const int t64  = tid & 63;
    const int bg   = t64 >> 3;          // 0..7
    const int jp   = t64 & 7;           // 0..7
    const int j0   = jblk * 16 + jp * 2;
    const int b0   = bg * 4;

    // stage W slice once
    const float* wsrc = g_whh_p[layer][dir] + (size_t)jblk * W_SM_FLOATS;
    for (int i = tid; i < W_SM_FLOATS / 4; i += 512)
        ((float4*)wsm)[i] = ((const float4*)wsrc)[i];

    const float* bhh = dir ? bhh_b : bhh_f;
    const float2 br  = *(const float2*)(bhh + j0);
    const float2 bz  = *(const float2*)(bhh + HH + j0);
    const float2 bn2 = *(const float2*)(bhh + 2 * HH + j0);
    const float* gx_base = g_gx[dir];
    __syncthreads();

    for (int t = 0; t < SS; t++) {
        const float* hprev = g_h[dir][t & 1];
        const int s_sel = dir ? (SS - 1 - t) : t;

        // gate-input prefetch (kg0 only; consumed after reduction)
        float2 xr[4], xz[4], xn[4];
        float4 hpa, hpb;
        if (kg == 0) {
#pragma unroll
            for (int bi = 0; bi < 4; bi++) {
                const float* gxp = gx_base + ((size_t)s_sel * BB + b0 + bi) * G3 + j0;
                xr[bi] = ldcg2(gxp);
                xz[bi] = ldcg2(gxp + HH);
                xn[bi] = ldcg2(gxp + 2 * HH);
            }
            hpa = ldcg4(hprev + j0 * BB + b0);
            hpb = ldcg4(hprev + (j0 + 1) * BB + b0);
        }

        // main accumulation over this group's 128 k
        const float* hk = hprev + (kg * 128) * BB + b0;
        const float* wk = wsm + (kg * 128) * 48 + jp * 2;
        float2 ar[4], az[4], an[4];
#pragma unroll
        for (int bi = 0; bi < 4; bi++) {
            ar[bi] = make_float2(0.f, 0.f);
            az[bi] = make_float2(0.f, 0.f);
            an[bi] = make_float2(0.f, 0.f);
        }

        float4 cur[4], nxt[4];
#pragma unroll
        for (int i = 0; i < 4; i++) cur[i] = ldcg4(hk + i * BB);

        for (int kk = 0; kk < 128; kk += 4) {
            if (kk < 124) {
#pragma unroll
                for (int i = 0; i < 4; i++) nxt[i] = ldcg4(hk + (kk + 4 + i) * BB);
            }
#pragma unroll
            for (int i = 0; i < 4; i++) {
                const float* w = wk + (kk + i) * 48;
                float2 wr = *(const float2*)(w);
                float2 wz = *(const float2*)(w + 16);
                float2 wn = *(const float2*)(w + 32);
                float4 h4 = cur[i];
                ar[0] = ffma2(bcast2(h4.x), wr, ar[0]);
                az[0] = ffma2(bcast2(h4.x), wz, az[0]);
                an[0] = ffma2(bcast2(h4.x), wn, an[0]);
                ar[1] = ffma2(bcast2(h4.y), wr, ar[1]);
                az[1] = ffma2(bcast2(h4.y), wz, az[1]);
                an[1] = ffma2(bcast2(h4.y), wn, an[1]);
                ar[2] = ffma2(bcast2(h4.z), wr, ar[2]);
                az[2] = ffma2(bcast2(h4.z), wz, az[2]);
                an[2] = ffma2(bcast2(h4.z), wn, an[2]);
                ar[3] = ffma2(bcast2(h4.w), wr, ar[3]);
                az[3] = ffma2(bcast2(h4.w), wz, az[3]);
                an[3] = ffma2(bcast2(h4.w), wn, an[3]);
            }
#pragma unroll
            for (int i = 0; i < 4; i++) cur[i] = nxt[i];
        }

        // k-split reduction: 8 -> 4 -> 2 -> 1 (slot layout [slot][lin][t64])
        __syncthreads();
        if (kg >= 4) {
            int base = (kg - 4) * 768;
#pragma unroll
            for (int bi = 0; bi < 4; bi++) {
                red[base + (bi * 3 + 0) * 64 + t64] = ar[bi];
                red[base + (bi * 3 + 1) * 64 + t64] = az[bi];
                red[base + (bi * 3 + 2) * 64 + t64] = an[bi];
            }
        }
        __syncthreads();
        if (kg < 4) {
            int base = kg * 768;
#pragma unroll
            for (int bi = 0; bi < 4; bi++) {
                float2 vr = red[base + (bi * 3 + 0) * 64 + t64];
                float2 vz = red[base + (bi * 3 + 1) * 64 + t64];
                float2 vn = red[base + (bi * 3 + 2) * 64 + t64];
                ar[bi].x += vr.x; ar[bi].y += vr.y;
                az[bi].x += vz.x; az[bi].y += vz.y;
                an[bi].x += vn.x; an[bi].y += vn.y;
            }
        }
        __syncthreads();
        if (kg == 2 || kg == 3) {
            int base = (kg - 2) * 768;
#pragma unroll
            for (int bi = 0; bi < 4; bi++) {
                red[base + (bi * 3 + 0) * 64 + t64] = ar[bi];
                red[base + (bi * 3 + 1) * 64 + t64] = az[bi];
                red[base + (bi * 3 + 2) * 64 + t64] = an[bi];
            }
        }
        __syncthreads();
        if (kg < 2) {
            int base = kg * 768;
#pragma unroll
            for (int bi = 0; bi < 4; bi++) {
                float2 vr = red[base + (bi * 3 + 0) * 64 + t64];
                float2 vz = red[base + (bi * 3 + 1) * 64 + t64];
                float2 vn = red[base + (bi * 3 + 2) * 64 + t64];
                ar[bi].x += vr.x; ar[bi].y += vr.y;
                az[bi].x += vz.x; az[bi].y += vz.y;
                an[bi].x += vn.x; an[bi].y += vn.y;
            }
        }
        __syncthreads();
        if (kg == 1) {
#pragma unroll
            for (int bi = 0; bi < 4; bi++) {
                red[(bi * 3 + 0) * 64 + t64] = ar[bi];
                red[(bi * 3 + 1) * 64 + t64] = az[bi];
                red[(bi * 3 + 2) * 64 + t64] = an[bi];
            }
        }
        __syncthreads();
        if (kg == 0) {
            float h0n[4], h1n[4];
#pragma unroll
            for (int bi = 0; bi < 4; bi++) {
                float2 vr = red[(bi * 3 + 0) * 64 + t64];
                float2 vz = red[(bi * 3 + 1) * 64 + t64];
                float2 vn = red[(bi * 3 + 2) * 64 + t64];
                float sr0 = xr[bi].x + ar[bi].x + vr.x + br.x;
                float sr1 = xr[bi].y + ar[bi].y + vr.y + br.y;
                float sz0 = xz[bi].x + az[bi].x + vz.x + bz.x;
                float sz1 = xz[bi].y + az[bi].y + vz.y + bz.y;
                float sn0 = an[bi].x + vn.x + bn2.x;
                float sn1 = an[bi].y + vn.y + bn2.y;
                float r0 = sigmoidf_(sr0), r1 = sigmoidf_(sr1);
                float z0 = sigmoidf_(sz0), z1 = sigmoidf_(sz1);
                float n0 = tanhf(xn[bi].x + r0 * sn0);
                float n1 = tanhf(xn[bi].y + r1 * sn1);
                float hp0 = (bi == 0) ? hpa.x : (bi == 1) ? hpa.y : (bi == 2) ? hpa.z : hpa.w;
                float hp1 = (bi == 0) ? hpb.x : (bi == 1) ? hpb.y : (bi == 2) ? hpb.z : hpb.w;
                h0n[bi] = (1.f - z0) * n0 + z0 * hp0;
                h1n[bi] = (1.f - z1) * n1 + z1 * hp1;
            }
            float* hout = g_h[dir][(t + 1) & 1];
            *(float4*)(hout + j0 * BB + b0) = make_float4(h0n[0], h0n[1], h0n[2], h0n[3]);
            *(float4*)(hout + (j0 + 1) * BB + b0) = make_float4(h1n[0], h1n[1], h1n[2], h1n[3]);
            if (layer == 0) {
#pragma unroll
                for (int bi = 0; bi < 4; bi++)
                    *(float2*)(&g_out0[((size_t)(b0 + bi) * SS + s_sel) * H2 + dir * HH + j0]) =
                        make_float2(h0n[bi], h1n[bi]);
            }
        }

        dir_barrier(dir, (unsigned)(t + 1));
    }
}

// ---------------- zero hidden + barrier state (between layers) ----------------
__global__ void zero_h_k() {
    int i = blockIdx.x * blockDim.x + threadIdx.x;
    if (i < HH * BB) { g_h[0][0][i] = 0.f; g_h[1][0][i] = 0.f; }
    if (i < 2) { g_bar_count[i] = 0u; g_bar_gen[i] = 0u; }
}

// ---------------- final output ----------------
__global__ void finalize_k(float* __restrict__ out) {
    int i = blockIdx.x * blockDim.x + threadIdx.x;
    if (i < BB * H2) {
        int b = i >> 11, c = i & 2047;
        out[i] = (c < HH) ? g_h[0][0][c * BB + b] : g_h[1][0][(c - HH) * BB + b];
    }
}

// ---------------- host ----------------
extern "C" void kernel_launch(void* const* d_in, const int* in_sizes, int n_in,
                              void* d_out, int out_size)
{
    const float* x       = (const float*)d_in[0];
    const float* w_ih_f0 = (const float*)d_in[1];
    const float* w_hh_f0 = (const float*)d_in[2];
    const float* b_ih_f0 = (const float*)d_in[3];
    const float* b_hh_f0 = (const float*)d_in[4];
    const float* w_ih_b0 = (const float*)d_in[5];
    const float* w_hh_b0 = (const float*)d_in[6];
    const float* b_ih_b0 = (const float*)d_in[7];
    const float* b_hh_b0 = (const float*)d_in[8];
    const float* w_ih_f1 = (const float*)d_in[9];
    const float* w_hh_f1 = (const float*)d_in[10];
    const float* b_ih_f1 = (const float*)d_in[11];
    const float* b_hh_f1 = (const float*)d_in[12];
    const float* w_ih_b1 = (const float*)d_in[13];
    const float* w_hh_b1 = (const float*)d_in[14];
    const float* b_ih_b1 = (const float*)d_in[15];
    const float* b_hh_b1 = (const float*)d_in[16];
    float* out = (float*)d_out;

    cudaFuncSetAttribute(gru_layer, cudaFuncAttributeMaxDynamicSharedMemorySize,
                         GRU_SMEM_BYTES);

    float *wih0, *wih1, *gx, *out0;
    cudaGetSymbolAddress((void**)&wih0, g_wih0_t);
    cudaGetSymbolAddress((void**)&wih1, g_wih1_t);
    cudaGetSymbolAddress((void**)&gx,   g_gx);
    cudaGetSymbolAddress((void**)&out0, g_out0);

    float* wih0_f = wih0;
    float* wih0_b = wih0 + (size_t)II * G3;
    float* wih1_f = wih1;
    float* wih1_b = wih1 + (size_t)H2 * G3;
    float* gx_f = gx;
    float* gx_b = gx + (size_t)BB * SS * G3;

    dim3 ggrid(G3 / 128, (BB * SS) / 128, 2);

    // #1
    transpose_ih<<<dim3(96, 64, 4), dim3(32, 8)>>>(
        w_ih_f0, w_ih_b0, w_ih_f1, w_ih_b1, wih0_f, wih0_b, wih1_f, wih1_b);
    // #2 (also zeroes h + barrier state)
    prepack_whh<<<dim3(12288, 4), 256>>>(w_hh_f0, w_hh_b0, w_hh_f1, w_hh_b1);
    // #3: layer0 gx for both dirs
    gemm_gx2<<<ggrid, 256>>>(x, SS * II, II, II, wih0_f, wih0_b,
                             b_ih_f0, b_ih_b0, gx_f, gx_b);
    // #4: layer0 recurrence (profiled slot)
    gru_layer<<<dim3(64, 2), 512, GRU_SMEM_BYTES>>>(0, b_hh_f0, b_hh_b0);

    // layer 1
    gemm_gx2<<<ggrid, 256>>>(out0, SS * H2, H2, H2, wih1_f, wih1_b,
                             b_ih_f1, b_ih_b1, gx_f, gx_b);
    zero_h_k<<<(HH * BB + 255) / 256, 256>>>();
    gru_layer<<<dim3(64, 2), 512, GRU_SMEM_BYTES>>>(1, b_hh_f1, b_hh_b1);

    finalize_k<<<(BB * H2 + 255) / 256, 256>>>(out);
}

// round 7
// speedup vs baseline: 3.1835x; 1.0004x over previous
#include <cuda_runtime.h>
#include <math.h>

#define BB 32
#define SS 512
#define II 512
#define HH 1024
#define G3 3072
#define H2 2048

#define W_SM_FLOATS (1024 * 48)       // per-CTA W slice: [k][3g][8jp] float2 = 196,608 B
#define RED_FLOAT2 (4 * 12 * 64)      // reduction buffer
#define GRU_SMEM_BYTES (W_SM_FLOATS * 4 + RED_FLOAT2 * 8)   // 221,184 B

// ---------------- device scratch ----------------
__device__ float g_wih0_t[2][II * G3];
__device__ float g_wih1_t[2][(size_t)H2 * G3];
__device__ float g_whh_p[2][2][HH * G3];
__device__ float g_gx[2][(size_t)BB * SS * G3];
__device__ float g_h[2][2][HH * BB];            // [dir][parity][j][b]
__device__ float g_out0[(size_t)BB * SS * H2];
__device__ unsigned g_bar_count[2];
__device__ unsigned g_bar_gen[2];

// ---------------- helpers ----------------
__device__ __forceinline__ float2 ffma2(float2 a, float2 b, float2 c) {
    unsigned long long A = *reinterpret_cast<unsigned long long*>(&a);
    unsigned long long B = *reinterpret_cast<unsigned long long*>(&b);
    unsigned long long C = *reinterpret_cast<unsigned long long*>(&c);
    unsigned long long D;
    asm("fma.rn.f32x2 %0, %1, %2, %3;" : "=l"(D) : "l"(A), "l"(B), "l"(C));
    return *reinterpret_cast<float2*>(&D);
}
__device__ __forceinline__ float2 bcast2(float x) { return make_float2(x, x); }
__device__ __forceinline__ float sigmoidf_(float x) { return 1.0f / (1.0f + expf(-x)); }

__device__ __forceinline__ float4 ldcg4(const float* p) {
    float4 v;
    asm volatile("ld.global.cg.v4.f32 {%0,%1,%2,%3}, [%4];"
                 : "=f"(v.x), "=f"(v.y), "=f"(v.z), "=f"(v.w) : "l"(p));
    return v;
}
__device__ __forceinline__ float2 ldcg2(const float* p) {
    float2 v;
    asm volatile("ld.global.cg.v2.f32 {%0,%1}, [%2];" : "=f"(v.x), "=f"(v.y) : "l"(p));
    return v;
}

// grid barrier per direction (64 CTAs), monotonic generation
__device__ __forceinline__ void dir_barrier(int dir, unsigned n) {
    __syncthreads();
    if (threadIdx.x == 0) {
        unsigned* cnt = &g_bar_count[dir];
        unsigned* gen = &g_bar_gen[dir];
        unsigned old;
        asm volatile("atom.acq_rel.gpu.global.add.u32 %0, [%1], 1;"
                     : "=r"(old) : "l"(cnt) : "memory");
        if (old == n * 64u - 1u) {
            asm volatile("red.release.gpu.global.add.u32 [%0], 1;" :: "l"(gen) : "memory");
        } else {
            unsigned cur;
            do {
                __nanosleep(16);
                asm volatile("ld.acquire.gpu.global.u32 %0, [%1];"
                             : "=r"(cur) : "l"(gen) : "memory");
            } while (cur < n);
        }
    }
    __syncthreads();
}

// ---------------- batched transpose for w_ih: in[3072][K] -> out[K][3072] ----------------
__global__ void transpose_ih(const float* f0, const float* b0,
                             const float* f1, const float* b1,
                             float* df0, float* db0, float* df1, float* db1) {
    __shared__ float tile[32][33];
    const float* in; float* out; int K;
    switch (blockIdx.z) {
        case 0: in = f0; out = df0; K = II; break;
        case 1: in = b0; out = db0; K = II; break;
        case 2: in = f1; out = df1; K = H2; break;
        default: in = b1; out = db1; K = H2; break;
    }
    int n0 = blockIdx.x * 32, k0 = blockIdx.y * 32;
    if (k0 >= K) return;
    for (int i = threadIdx.y; i < 32; i += 8)
        tile[i][threadIdx.x] = in[(size_t)(n0 + i) * K + k0 + threadIdx.x];
    __syncthreads();
    for (int i = threadIdx.y; i < 32; i += 8)
        out[(size_t)(k0 + i) * G3 + n0 + threadIdx.x] = tile[threadIdx.x][i];
}

// ---------------- prepack W_hh into [jblk][k][g][jp][c] + zero h / barriers ----------------
__global__ void prepack_whh(const float* w00, const float* w01,
                            const float* w10, const float* w11) {
    int mat = blockIdx.y;
    const float* src = (mat == 0) ? w00 : (mat == 1) ? w01 : (mat == 2) ? w10 : w11;
    float* dst = g_whh_p[mat >> 1][mat & 1];
    int idx = blockIdx.x * 256 + threadIdx.x;   // n*1024 + k
    int k = idx & 1023;
    int n = idx >> 10;
    int g = n >> 10;
    int nj = n & 1023;
    int jblk = nj >> 4;
    int jp = (nj >> 1) & 7;
    int c  = nj & 1;
    dst[jblk * W_SM_FLOATS + k * 48 + g * 16 + jp * 2 + c] = src[idx];
    if (mat == 0) {
        if (idx < HH * BB) { g_h[0][0][idx] = 0.f; g_h[1][0][idx] = 0.f; }
        if (idx < 2) { g_bar_count[idx] = 0u; g_bar_gen[idx] = 0u; }
    }
}

// ---------------- SGEMM 128x128x16, double-buffered, 2 CTAs/SM ----------------
__global__ __launch_bounds__(256, 2) void gemm_gx2(
    const float* __restrict__ X, int strideB, int strideS, int K,
    const float* __restrict__ Wt0, const float* __restrict__ Wt1,
    const float* __restrict__ bias0, const float* __restrict__ bias1,
    float* __restrict__ C0, float* __restrict__ C1)
{
    __shared__ float As[2][16][128];
    __shared__ float Bs[2][16][128];
    const float* Wt   = blockIdx.z ? Wt1 : Wt0;
    const float* bias = blockIdx.z ? bias1 : bias0;
    float* C          = blockIdx.z ? C1 : C0;

    const int tid = threadIdx.x;
    const int bn = blockIdx.x * 128;
    const int bm = blockIdx.y * 128;
    const int tx = tid & 15, ty = tid >> 4;

    const int rowA0 = tid >> 2;            // 0..63
    const int rowA1 = rowA0 + 64;
    const int qa = tid & 3;
    int m0 = bm + rowA0, m1 = bm + rowA1;
    const float* Xr0 = X + (size_t)(m0 & 31) * strideB + (size_t)(m0 >> 5) * strideS + qa * 4;
    const float* Xr1 = X + (size_t)(m1 & 31) * strideB + (size_t)(m1 >> 5) * strideS + qa * 4;
    const int krB = tid >> 5;              // 0..7
    const int nqB = tid & 31;
    const float* Wp0 = Wt + (size_t)krB * G3 + bn + nqB * 4;
    const float* Wp1 = Wt + (size_t)(krB + 8) * G3 + bn + nqB * 4;

    float2 acc[8][4];
#pragma unroll
    for (int i = 0; i < 8; i++)
#pragma unroll
        for (int j = 0; j < 4; j++) acc[i][j] = make_float2(0.f, 0.f);

    // prologue: tile 0
    float4 ra0 = *(const float4*)(Xr0);
    float4 ra1 = *(const float4*)(Xr1);
    float4 rb0 = *(const float4*)(Wp0);
    float4 rb1 = *(const float4*)(Wp1);
    As[0][qa * 4 + 0][rowA0] = ra0.x;
    As[0][qa * 4 + 1][rowA0] = ra0.y;
    As[0][qa * 4 + 2][rowA0] = ra0.z;
    As[0][qa * 4 + 3][rowA0] = ra0.w;
    As[0][qa * 4 + 0][rowA1] = ra1.x;
    As[0][qa * 4 + 1][rowA1] = ra1.y;
    As[0][qa * 4 + 2][rowA1] = ra1.z;
    As[0][qa * 4 + 3][rowA1] = ra1.w;
    *(float4*)&Bs[0][krB][nqB * 4] = rb0;
    *(float4*)&Bs[0][krB + 8][nqB * 4] = rb1;
    __syncthreads();

    int buf = 0;
    for (int k0 = 0; k0 < K; k0 += 16) {
        const bool more = (k0 + 16 < K);
        if (more) {
            ra0 = *(const float4*)(Xr0 + k0 + 16);
            ra1 = *(const float4*)(Xr1 + k0 + 16);
            rb0 = *(const float4*)(Wp0 + (size_t)(k0 + 16) * G3);
            rb1 = *(const float4*)(Wp1 + (size_t)(k0 + 16) * G3);
        }
#pragma unroll
        for (int kk = 0; kk < 16; kk++) {
            float4 av0 = *(const float4*)&As[buf][kk][ty * 8];
            float4 av1 = *(const float4*)&As[buf][kk][ty * 8 + 4];
            float4 bv0 = *(const float4*)&Bs[buf][kk][tx * 8];
            float4 bv1 = *(const float4*)&Bs[buf][kk][tx * 8 + 4];
            float aa[8] = {av0.x, av0.y, av0.z, av0.w, av1.x, av1.y, av1.z, av1.w};
            float2 bb[4] = {make_float2(bv0.x, bv0.y), make_float2(bv0.z, bv0.w),
                            make_float2(bv1.x, bv1.y), make_float2(bv1.z, bv1.w)};
#pragma unroll
            for (int i = 0; i < 8; i++) {
                float2 a2 = make_float2(aa[i], aa[i]);
#pragma unroll
                for (int j = 0; j < 4; j++) acc[i][j] = ffma2(a2, bb[j], acc[i][j]);
            }
        }
        if (more) {
            int nb = buf ^ 1;
            As[nb][qa * 4 + 0][rowA0] = ra0.x;
            As[nb][qa * 4 + 1][rowA0] = ra0.y;
            As[nb][qa * 4 + 2][rowA0] = ra0.z;
            As[nb][qa * 4 + 3][rowA0] = ra0.w;
            As[nb][qa * 4 + 0][rowA1] = ra1.x;
            As[nb][qa * 4 + 1][rowA1] = ra1.y;
            As[nb][qa * 4 + 2][rowA1] = ra1.z;
            As[nb][qa * 4 + 3][rowA1] = ra1.w;
            *(float4*)&Bs[nb][krB][nqB * 4] = rb0;
            *(float4*)&Bs[nb][krB + 8][nqB * 4] = rb1;
            __syncthreads();
            buf = nb;
        }
    }

    float4 bsv0 = *(const float4*)(bias + bn + tx * 8);
    float4 bsv1 = *(const float4*)(bias + bn + tx * 8 + 4);
    float bv[8] = {bsv0.x, bsv0.y, bsv0.z, bsv0.w, bsv1.x, bsv1.y, bsv1.z, bsv1.w};
#pragma unroll
    for (int i = 0; i < 8; i++) {
        int m2 = bm + ty * 8 + i;
        float* crow = C + (size_t)m2 * G3 + bn + tx * 8;
        float4 v0 = make_float4(acc[i][0].x + bv[0], acc[i][0].y + bv[1],
                                acc[i][1].x + bv[2], acc[i][1].y + bv[3]);
        float4 v1 = make_float4(acc[i][2].x + bv[4], acc[i][2].y + bv[5],
                                acc[i][3].x + bv[6], acc[i][3].y + bv[7]);
        *(float4*)(crow) = v0;
        *(float4*)(crow + 4) = v1;
    }
}

// ---------------- persistent recurrent layer (batch-blocked, k-split 8) ----------------
__global__ __launch_bounds__(512, 1) void gru_layer(
    int layer, const float* __restrict__ bhh_f, const float* __restrict__ bhh_b)
{
    extern __shared__ float smem[];
    float* wsm  = smem;
    float2* red = (float2*)(smem + W_SM_FLOATS);

    const int dir  = blockIdx.y;
    const int jblk = blockIdx.x;
    const int tid  = threadIdx.x;
    const int kg   = tid >> 6;
    const int t64  = tid & 63;
    const int bg   = t64 >> 3;
    const int jp   = t64 & 7;
    const int j0   = jblk * 16 + jp * 2;
    const int b0   = bg * 4;

    const float* wsrc = g_whh_p[layer][dir] + (size_t)jblk * W_SM_FLOATS;
    for (int i = tid; i < W_SM_FLOATS / 4; i += 512)
        ((float4*)wsm)[i] = ((const float4*)wsrc)[i];

    const float* bhh = dir ? bhh_b : bhh_f;
    const float2 br  = *(const float2*)(bhh + j0);
    const float2 bz  = *(const float2*)(bhh + HH + j0);
    const float2 bn2 = *(const float2*)(bhh + 2 * HH + j0);
    const float* gx_base = g_gx[dir];
    __syncthreads();

    for (int t = 0; t < SS; t++) {
        const float* hprev = g_h[dir][t & 1];
        const int s_sel = dir ? (SS - 1 - t) : t;

        float2 xr[4], xz[4], xn[4];
        float4 hpa, hpb;
        if (kg == 0) {
#pragma unroll
            for (int bi = 0; bi < 4; bi++) {
                const float* gxp = gx_base + ((size_t)s_sel * BB + b0 + bi) * G3 + j0;
                xr[bi] = ldcg2(gxp);
                xz[bi] = ldcg2(gxp + HH);
                xn[bi] = ldcg2(gxp + 2 * HH);
            }
            hpa = ldcg4(hprev + j0 * BB + b0);
            hpb = ldcg4(hprev + (j0 + 1) * BB + b0);
        }

        const float* hk = hprev + (kg * 128) * BB + b0;
        const float* wk = wsm + (kg * 128) * 48 + jp * 2;
        float2 ar[4], az[4], an[4];
#pragma unroll
        for (int bi = 0; bi < 4; bi++) {
            ar[bi] = make_float2(0.f, 0.f);
            az[bi] = make_float2(0.f, 0.f);
            an[bi] = make_float2(0.f, 0.f);
        }

        float4 cur[4], nxt[4];
#pragma unroll
        for (int i = 0; i < 4; i++) cur[i] = ldcg4(hk + i * BB);

        for (int kk = 0; kk < 128; kk += 4) {
            if (kk < 124) {
#pragma unroll
                for (int i = 0; i < 4; i++) nxt[i] = ldcg4(hk + (kk + 4 + i) * BB);
            }
#pragma unroll
            for (int i = 0; i < 4; i++) {
                const float* w = wk + (kk + i) * 48;
                float2 wr = *(const float2*)(w);
                float2 wz = *(const float2*)(w + 16);
                float2 wn = *(const float2*)(w + 32);
                float4 h4 = cur[i];
                ar[0] = ffma2(bcast2(h4.x), wr, ar[0]);
                az[0] = ffma2(bcast2(h4.x), wz, az[0]);
                an[0] = ffma2(bcast2(h4.x), wn, an[0]);
                ar[1] = ffma2(bcast2(h4.y), wr, ar[1]);
                az[1] = ffma2(bcast2(h4.y), wz, az[1]);
                an[1] = ffma2(bcast2(h4.y), wn, an[1]);
                ar[2] = ffma2(bcast2(h4.z), wr, ar[2]);
                az[2] = ffma2(bcast2(h4.z), wz, az[2]);
                an[2] = ffma2(bcast2(h4.z), wn, an[2]);
                ar[3] = ffma2(bcast2(h4.w), wr, ar[3]);
                az[3] = ffma2(bcast2(h4.w), wz, az[3]);
                an[3] = ffma2(bcast2(h4.w), wn, an[3]);
            }
#pragma unroll
            for (int i = 0; i < 4; i++) cur[i] = nxt[i];
        }

        __syncthreads();
        if (kg >= 4) {
            int base = (kg - 4) * 768;
#pragma unroll
            for (int bi = 0; bi < 4; bi++) {
                red[base + (bi * 3 + 0) * 64 + t64] = ar[bi];
                red[base + (bi * 3 + 1) * 64 + t64] = az[bi];
                red[base + (bi * 3 + 2) * 64 + t64] = an[bi];
            }
        }
        __syncthreads();
        if (kg < 4) {
            int base = kg * 768;
#pragma unroll
            for (int bi = 0; bi < 4; bi++) {
                float2 vr = red[base + (bi * 3 + 0) * 64 + t64];
                float2 vz = red[base + (bi * 3 + 1) * 64 + t64];
                float2 vn = red[base + (bi * 3 + 2) * 64 + t64];
                ar[bi].x += vr.x; ar[bi].y += vr.y;
                az[bi].x += vz.x; az[bi].y += vz.y;
                an[bi].x += vn.x; an[bi].y += vn.y;
            }
        }
        __syncthreads();
        if (kg == 2 || kg == 3) {
            int base = (kg - 2) * 768;
#pragma unroll
            for (int bi = 0; bi < 4; bi++) {
                red[base + (bi * 3 + 0) * 64 + t64] = ar[bi];
                red[base + (bi * 3 + 1) * 64 + t64] = az[bi];
                red[base + (bi * 3 + 2) * 64 + t64] = an[bi];
            }
        }
        __syncthreads();
        if (kg < 2) {
            int base = kg * 768;
#pragma unroll
            for (int bi = 0; bi < 4; bi++) {
                float2 vr = red[base + (bi * 3 + 0) * 64 + t64];
                float2 vz = red[base + (bi * 3 + 1) * 64 + t64];
                float2 vn = red[base + (bi * 3 + 2) * 64 + t64];
                ar[bi].x += vr.x; ar[bi].y += vr.y;
                az[bi].x += vz.x; az[bi].y += vz.y;
                an[bi].x += vn.x; an[bi].y += vn.y;
            }
        }
        __syncthreads();
        if (kg == 1) {
#pragma unroll
            for (int bi = 0; bi < 4; bi++) {
                red[(bi * 3 + 0) * 64 + t64] = ar[bi];
                red[(bi * 3 + 1) * 64 + t64] = az[bi];
                red[(bi * 3 + 2) * 64 + t64] = an[bi];
            }
        }
        __syncthreads();
        if (kg == 0) {
            float h0n[4], h1n[4];
#pragma unroll
            for (int bi = 0; bi < 4; bi++) {
                float2 vr = red[(bi * 3 + 0) * 64 + t64];
                float2 vz = red[(bi * 3 + 1) * 64 + t64];
                float2 vn = red[(bi * 3 + 2) * 64 + t64];
                float sr0 = xr[bi].x + ar[bi].x + vr.x + br.x;
                float sr1 = xr[bi].y + ar[bi].y + vr.y + br.y;
                float sz0 = xz[bi].x + az[bi].x + vz.x + bz.x;
                float sz1 = xz[bi].y + az[bi].y + vz.y + bz.y;
                float sn0 = an[bi].x + vn.x + bn2.x;
                float sn1 = an[bi].y + vn.y + bn2.y;
                float r0 = sigmoidf_(sr0), r1 = sigmoidf_(sr1);
                float z0 = sigmoidf_(sz0), z1 = sigmoidf_(sz1);
                float n0 = tanhf(xn[bi].x + r0 * sn0);
                float n1 = tanhf(xn[bi].y + r1 * sn1);
                float hp0 = (bi == 0) ? hpa.x : (bi == 1) ? hpa.y : (bi == 2) ? hpa.z : hpa.w;
                float hp1 = (bi == 0) ? hpb.x : (bi == 1) ? hpb.y : (bi == 2) ? hpb.z : hpb.w;
                h0n[bi] = (1.f - z0) * n0 + z0 * hp0;
                h1n[bi] = (1.f - z1) * n1 + z1 * hp1;
            }
            float* hout = g_h[dir][(t + 1) & 1];
            *(float4*)(hout + j0 * BB + b0) = make_float4(h0n[0], h0n[1], h0n[2], h0n[3]);
            *(float4*)(hout + (j0 + 1) * BB + b0) = make_float4(h1n[0], h1n[1], h1n[2], h1n[3]);
            if (layer == 0) {
#pragma unroll
                for (int bi = 0; bi < 4; bi++)
                    *(float2*)(&g_out0[((size_t)(b0 + bi) * SS + s_sel) * H2 + dir * HH + j0]) =
                        make_float2(h0n[bi], h1n[bi]);
            }
        }

        dir_barrier(dir, (unsigned)(t + 1));
    }
}

// ---------------- zero hidden + barrier state (between layers) ----------------
__global__ void zero_h_k() {
    int i = blockIdx.x * blockDim.x + threadIdx.x;
    if (i < HH * BB) { g_h[0][0][i] = 0.f; g_h[1][0][i] = 0.f; }
    if (i < 2) { g_bar_count[i] = 0u; g_bar_gen[i] = 0u; }
}

// ---------------- final output ----------------
__global__ void finalize_k(float* __restrict__ out) {
    int i = blockIdx.x * blockDim.x + threadIdx.x;
    if (i < BB * H2) {
        int b = i >> 11, c = i & 2047;
        out[i] = (c < HH) ? g_h[0][0][c * BB + b] : g_h[1][0][(c - HH) * BB + b];
    }
}

// ---------------- host ----------------
extern "C" void kernel_launch(void* const* d_in, const int* in_sizes, int n_in,
                              void* d_out, int out_size)
{
    const float* x       = (const float*)d_in[0];
    const float* w_ih_f0 = (const float*)d_in[1];
    const float* w_hh_f0 = (const float*)d_in[2];
    const float* b_ih_f0 = (const float*)d_in[3];
    const float* b_hh_f0 = (const float*)d_in[4];
    const float* w_ih_b0 = (const float*)d_in[5];
    const float* w_hh_b0 = (const float*)d_in[6];
    const float* b_ih_b0 = (const float*)d_in[7];
    const float* b_hh_b0 = (const float*)d_in[8];
    const float* w_ih_f1 = (const float*)d_in[9];
    const float* w_hh_f1 = (const float*)d_in[10];
    const float* b_ih_f1 = (const float*)d_in[11];
    const float* b_hh_f1 = (const float*)d_in[12];
    const float* w_ih_b1 = (const float*)d_in[13];
    const float* w_hh_b1 = (const float*)d_in[14];
    const float* b_ih_b1 = (const float*)d_in[15];
    const float* b_hh_b1 = (const float*)d_in[16];
    float* out = (float*)d_out;

    cudaFuncSetAttribute(gru_layer, cudaFuncAttributeMaxDynamicSharedMemorySize,
                         GRU_SMEM_BYTES);

    float *wih0, *wih1, *gx, *out0;
    cudaGetSymbolAddress((void**)&wih0, g_wih0_t);
    cudaGetSymbolAddress((void**)&wih1, g_wih1_t);
    cudaGetSymbolAddress((void**)&gx,   g_gx);
    cudaGetSymbolAddress((void**)&out0, g_out0);

    float* wih0_f = wih0;
    float* wih0_b = wih0 + (size_t)II * G3;
    float* wih1_f = wih1;
    float* wih1_b = wih1 + (size_t)H2 * G3;
    float* gx_f = gx;
    float* gx_b = gx + (size_t)BB * SS * G3;

    dim3 ggrid(G3 / 128, (BB * SS) / 128, 2);

    transpose_ih<<<dim3(96, 64, 4), dim3(32, 8)>>>(
        w_ih_f0, w_ih_b0, w_ih_f1, w_ih_b1, wih0_f, wih0_b, wih1_f, wih1_b);
    prepack_whh<<<dim3(12288, 4), 256>>>(w_hh_f0, w_hh_b0, w_hh_f1, w_hh_b1);
    gemm_gx2<<<ggrid, 256>>>(x, SS * II, II, II, wih0_f, wih0_b,
                             b_ih_f0, b_ih_b0, gx_f, gx_b);
    gru_layer<<<dim3(64, 2), 512, GRU_SMEM_BYTES>>>(0, b_hh_f0, b_hh_b0);

    gemm_gx2<<<ggrid, 256>>>(out0, SS * H2, H2, H2, wih1_f, wih1_b,
                             b_ih_f1, b_ih_b1, gx_f, gx_b);
    zero_h_k<<<(HH * BB + 255) / 256, 256>>>();
    gru_layer<<<dim3(64, 2), 512, GRU_SMEM_BYTES>>>(1, b_hh_f1, b_hh_b1);

    finalize_k<<<(BB * H2 + 255) / 256, 256>>>(out);
}

// round 8
// speedup vs baseline: 3.3105x; 1.0399x over previous
#include <cuda_runtime.h>
#include <math.h>

#define BB 32
#define SS 512
#define II 512
#define HH 1024
#define G3 3072
#define H2 2048

#define W_SM_FLOATS (1024 * 48)         // per-CTA W slice: 196,608 B
#define HSTAGE_FLOATS (8 * 2 * 512)     // 8 groups x 2 bufs x (16k x 32b) = 32 KB
#define GRU_SMEM_BYTES ((W_SM_FLOATS + HSTAGE_FLOATS) * 4)   // 229,376 B

// ---------------- device scratch ----------------
__device__ float g_wih0_t[2][II * G3];
__device__ float g_wih1_t[2][(size_t)H2 * G3];
__device__ float g_whh_p[2][2][HH * G3];
__device__ float g_gx[2][(size_t)BB * SS * G3];
__device__ float g_h[2][2][HH * BB];            // [dir][parity][j][b]
__device__ float g_out0[(size_t)BB * SS * H2];
__device__ unsigned g_bar_count[2];
__device__ unsigned g_bar_gen[2];

// ---------------- helpers ----------------
__device__ __forceinline__ float2 ffma2(float2 a, float2 b, float2 c) {
    unsigned long long A = *reinterpret_cast<unsigned long long*>(&a);
    unsigned long long B = *reinterpret_cast<unsigned long long*>(&b);
    unsigned long long C = *reinterpret_cast<unsigned long long*>(&c);
    unsigned long long D;
    asm("fma.rn.f32x2 %0, %1, %2, %3;" : "=l"(D) : "l"(A), "l"(B), "l"(C));
    return *reinterpret_cast<float2*>(&D);
}
__device__ __forceinline__ float2 bcast2(float x) { return make_float2(x, x); }
__device__ __forceinline__ float sigmoidf_(float x) { return 1.0f / (1.0f + expf(-x)); }

__device__ __forceinline__ float4 ldcg4(const float* p) {
    float4 v;
    asm volatile("ld.global.cg.v4.f32 {%0,%1,%2,%3}, [%4];"
                 : "=f"(v.x), "=f"(v.y), "=f"(v.z), "=f"(v.w) : "l"(p));
    return v;
}
__device__ __forceinline__ float2 ldcg2(const float* p) {
    float2 v;
    asm volatile("ld.global.cg.v2.f32 {%0,%1}, [%2];" : "=f"(v.x), "=f"(v.y) : "l"(p));
    return v;
}
__device__ __forceinline__ void cpasync16(unsigned dst, const float* src) {
    asm volatile("cp.async.cg.shared.global [%0], [%1], 16;" :: "r"(dst), "l"(src) : "memory");
}

// grid barrier per direction (64 CTAs), monotonic generation
__device__ __forceinline__ void dir_barrier(int dir, unsigned n) {
    __syncthreads();
    if (threadIdx.x == 0) {
        unsigned* cnt = &g_bar_count[dir];
        unsigned* gen = &g_bar_gen[dir];
        unsigned old;
        asm volatile("atom.acq_rel.gpu.global.add.u32 %0, [%1], 1;"
                     : "=r"(old) : "l"(cnt) : "memory");
        if (old == n * 64u - 1u) {
            asm volatile("red.release.gpu.global.add.u32 [%0], 1;" :: "l"(gen) : "memory");
        } else {
            unsigned cur;
            do {
                __nanosleep(16);
                asm volatile("ld.acquire.gpu.global.u32 %0, [%1];"
                             : "=r"(cur) : "l"(gen) : "memory");
            } while (cur < n);
        }
    }
    __syncthreads();
}

// ---------------- batched transpose for w_ih: in[3072][K] -> out[K][3072] ----------------
__global__ void transpose_ih(const float* f0, const float* b0,
                             const float* f1, const float* b1,
                             float* df0, float* db0, float* df1, float* db1) {
    __shared__ float tile[32][33];
    const float* in; float* out; int K;
    switch (blockIdx.z) {
        case 0: in = f0; out = df0; K = II; break;
        case 1: in = b0; out = db0; K = II; break;
        case 2: in = f1; out = df1; K = H2; break;
        default: in = b1; out = db1; K = H2; break;
    }
    int n0 = blockIdx.x * 32, k0 = blockIdx.y * 32;
    if (k0 >= K) return;
    for (int i = threadIdx.y; i < 32; i += 8)
        tile[i][threadIdx.x] = in[(size_t)(n0 + i) * K + k0 + threadIdx.x];
    __syncthreads();
    for (int i = threadIdx.y; i < 32; i += 8)
        out[(size_t)(k0 + i) * G3 + n0 + threadIdx.x] = tile[threadIdx.x][i];
}

// ---------------- prepack W_hh into [jblk][k][g][jp][c] + zero h / barriers ----------------
__global__ void prepack_whh(const float* w00, const float* w01,
                            const float* w10, const float* w11) {
    int mat = blockIdx.y;
    const float* src = (mat == 0) ? w00 : (mat == 1) ? w01 : (mat == 2) ? w10 : w11;
    float* dst = g_whh_p[mat >> 1][mat & 1];
    int idx = blockIdx.x * 256 + threadIdx.x;   // n*1024 + k
    int k = idx & 1023;
    int n = idx >> 10;
    int g = n >> 10;
    int nj = n & 1023;
    int jblk = nj >> 4;
    int jp = (nj >> 1) & 7;
    int c  = nj & 1;
    dst[jblk * W_SM_FLOATS + k * 48 + g * 16 + jp * 2 + c] = src[idx];
    if (mat == 0) {
        if (idx < HH * BB) { g_h[0][0][idx] = 0.f; g_h[1][0][idx] = 0.f; }
        if (idx < 2) { g_bar_count[idx] = 0u; g_bar_gen[idx] = 0u; }
    }
}

// ---------------- SGEMM 128x128x16, double-buffered, 2 CTAs/SM ----------------
__global__ __launch_bounds__(256, 2) void gemm_gx2(
    const float* __restrict__ X, int strideB, int strideS, int K,
    const float* __restrict__ Wt0, const float* __restrict__ Wt1,
    const float* __restrict__ bias0, const float* __restrict__ bias1,
    float* __restrict__ C0, float* __restrict__ C1)
{
    __shared__ float As[2][16][128];
    __shared__ float Bs[2][16][128];
    const float* Wt   = blockIdx.z ? Wt1 : Wt0;
    const float* bias = blockIdx.z ? bias1 : bias0;
    float* C          = blockIdx.z ? C1 : C0;

    const int tid = threadIdx.x;
    const int bn = blockIdx.x * 128;
    const int bm = blockIdx.y * 128;
    const int tx = tid & 15, ty = tid >> 4;

    const int rowA0 = tid >> 2;
    const int rowA1 = rowA0 + 64;
    const int qa = tid & 3;
    int m0 = bm + rowA0, m1 = bm + rowA1;
    const float* Xr0 = X + (size_t)(m0 & 31) * strideB + (size_t)(m0 >> 5) * strideS + qa * 4;
    const float* Xr1 = X + (size_t)(m1 & 31) * strideB + (size_t)(m1 >> 5) * strideS + qa * 4;
    const int krB = tid >> 5;
    const int nqB = tid & 31;
    const float* Wp0 = Wt + (size_t)krB * G3 + bn + nqB * 4;
    const float* Wp1 = Wt + (size_t)(krB + 8) * G3 + bn + nqB * 4;

    float2 acc[8][4];
#pragma unroll
    for (int i = 0; i < 8; i++)
#pragma unroll
        for (int j = 0; j < 4; j++) acc[i][j] = make_float2(0.f, 0.f);

    float4 ra0 = *(const float4*)(Xr0);
    float4 ra1 = *(const float4*)(Xr1);
    float4 rb0 = *(const float4*)(Wp0);
    float4 rb1 = *(const float4*)(Wp1);
    As[0][qa * 4 + 0][rowA0] = ra0.x;
    As[0][qa * 4 + 1][rowA0] = ra0.y;
    As[0][qa * 4 + 2][rowA0] = ra0.z;
    As[0][qa * 4 + 3][rowA0] = ra0.w;
    As[0][qa * 4 + 0][rowA1] = ra1.x;
    As[0][qa * 4 + 1][rowA1] = ra1.y;
    As[0][qa * 4 + 2][rowA1] = ra1.z;
    As[0][qa * 4 + 3][rowA1] = ra1.w;
    *(float4*)&Bs[0][krB][nqB * 4] = rb0;
    *(float4*)&Bs[0][krB + 8][nqB * 4] = rb1;
    __syncthreads();

    int buf = 0;
    for (int k0 = 0; k0 < K; k0 += 16) {
        const bool more = (k0 + 16 < K);
        if (more) {
            ra0 = *(const float4*)(Xr0 + k0 + 16);
            ra1 = *(const float4*)(Xr1 + k0 + 16);
            rb0 = *(const float4*)(Wp0 + (size_t)(k0 + 16) * G3);
            rb1 = *(const float4*)(Wp1 + (size_t)(k0 + 16) * G3);
        }
#pragma unroll
        for (int kk = 0; kk < 16; kk++) {
            float4 av0 = *(const float4*)&As[buf][kk][ty * 8];
            float4 av1 = *(const float4*)&As[buf][kk][ty * 8 + 4];
            float4 bv0 = *(const float4*)&Bs[buf][kk][tx * 8];
            float4 bv1 = *(const float4*)&Bs[buf][kk][tx * 8 + 4];
            float aa[8] = {av0.x, av0.y, av0.z, av0.w, av1.x, av1.y, av1.z, av1.w};
            float2 bb[4] = {make_float2(bv0.x, bv0.y), make_float2(bv0.z, bv0.w),
                            make_float2(bv1.x, bv1.y), make_float2(bv1.z, bv1.w)};
#pragma unroll
            for (int i = 0; i < 8; i++) {
                float2 a2 = make_float2(aa[i], aa[i]);
#pragma unroll
                for (int j = 0; j < 4; j++) acc[i][j] = ffma2(a2, bb[j], acc[i][j]);
            }
        }
        if (more) {
            int nb = buf ^ 1;
            As[nb][qa * 4 + 0][rowA0] = ra0.x;
            As[nb][qa * 4 + 1][rowA0] = ra0.y;
            As[nb][qa * 4 + 2][rowA0] = ra0.z;
            As[nb][qa * 4 + 3][rowA0] = ra0.w;
            As[nb][qa * 4 + 0][rowA1] = ra1.x;
            As[nb][qa * 4 + 1][rowA1] = ra1.y;
            As[nb][qa * 4 + 2][rowA1] = ra1.z;
            As[nb][qa * 4 + 3][rowA1] = ra1.w;
            *(float4*)&Bs[nb][krB][nqB * 4] = rb0;
            *(float4*)&Bs[nb][krB + 8][nqB * 4] = rb1;
            __syncthreads();
            buf = nb;
        }
    }

    float4 bsv0 = *(const float4*)(bias + bn + tx * 8);
    float4 bsv1 = *(const float4*)(bias + bn + tx * 8 + 4);
    float bv[8] = {bsv0.x, bsv0.y, bsv0.z, bsv0.w, bsv1.x, bsv1.y, bsv1.z, bsv1.w};
#pragma unroll
    for (int i = 0; i < 8; i++) {
        int m2 = bm + ty * 8 + i;
        float* crow = C + (size_t)m2 * G3 + bn + tx * 8;
        float4 v0 = make_float4(acc[i][0].x + bv[0], acc[i][0].y + bv[1],
                                acc[i][1].x + bv[2], acc[i][1].y + bv[3]);
        float4 v1 = make_float4(acc[i][2].x + bv[4], acc[i][2].y + bv[5],
                                acc[i][3].x + bv[6], acc[i][3].y + bv[7]);
        *(float4*)(crow) = v0;
        *(float4*)(crow + 4) = v1;
    }
}

// ---------------- persistent recurrent layer (cp.async staged h) ----------------
// grid (64 jblks, 2 dirs), 512 thr: tid = kg*64 + bg*8 + jp.
// Each kg group stages its own 128-k slice in 16k x 32b chunks (2 KB), double-buffered.
__global__ __launch_bounds__(512, 1) void gru_layer(
    int layer, const float* __restrict__ bhh_f, const float* __restrict__ bhh_b)
{
    extern __shared__ float smem[];
    float* wsm  = smem;
    float2* red = (float2*)(smem + W_SM_FLOATS);   // overlays h staging (safe: disjoint in time)

    const int dir  = blockIdx.y;
    const int jblk = blockIdx.x;
    const int tid  = threadIdx.x;
    const int kg   = tid >> 6;
    const int t64  = tid & 63;
    const int bg   = t64 >> 3;
    const int jp   = t64 & 7;
    const int j0   = jblk * 16 + jp * 2;
    const int b0   = bg * 4;

    const float* wsrc = g_whh_p[layer][dir] + (size_t)jblk * W_SM_FLOATS;
    for (int i = tid; i < W_SM_FLOATS / 4; i += 512)
        ((float4*)wsm)[i] = ((const float4*)wsrc)[i];

    const float* bhh = dir ? bhh_b : bhh_f;
    const float2 br  = *(const float2*)(bhh + j0);
    const float2 bz  = *(const float2*)(bhh + HH + j0);
    const float2 bn2 = *(const float2*)(bhh + 2 * HH + j0);
    const float* gx_base = g_gx[dir];

    // this group's staging region: byte address + generic pointer
    float* hst_grp = smem + W_SM_FLOATS + kg * 1024;
    const unsigned hstg = (unsigned)__cvta_generic_to_shared(hst_grp);
    __syncthreads();

    for (int t = 0; t < SS; t++) {
        const float* hprev = g_h[dir][t & 1];
        const int s_sel = dir ? (SS - 1 - t) : t;
        const float* hsrc = hprev + kg * 128 * BB;   // this group's 128-k slice (contiguous)

        // prologue: stage chunks 0, 1 (each chunk = 512 floats; 2 x 16B per thread)
#pragma unroll
        for (int pc = 0; pc < 2; pc++) {
            unsigned dst = hstg + pc * 2048 + t64 * 16;
            const float* src = hsrc + pc * 512 + t64 * 4;
            cpasync16(dst, src);
            cpasync16(dst + 1024, src + 256);
            asm volatile("cp.async.commit_group;" ::: "memory");
        }

        // gate-input prefetch (kg0 only; consumed after reduction)
        float2 xr[4], xz[4], xn[4];
        float4 hpa, hpb;
        if (kg == 0) {
#pragma unroll
            for (int bi = 0; bi < 4; bi++) {
                const float* gxp = gx_base + ((size_t)s_sel * BB + b0 + bi) * G3 + j0;
                xr[bi] = ldcg2(gxp);
                xz[bi] = ldcg2(gxp + HH);
                xn[bi] = ldcg2(gxp + 2 * HH);
            }
            hpa = ldcg4(hprev + j0 * BB + b0);
            hpb = ldcg4(hprev + (j0 + 1) * BB + b0);
        }

        float2 ar[4], az[4], an[4];
#pragma unroll
        for (int bi = 0; bi < 4; bi++) {
            ar[bi] = make_float2(0.f, 0.f);
            az[bi] = make_float2(0.f, 0.f);
            an[bi] = make_float2(0.f, 0.f);
        }

#pragma unroll
        for (int c = 0; c < 8; c++) {
            if (c < 7) asm volatile("cp.async.wait_group 1;" ::: "memory");
            else       asm volatile("cp.async.wait_group 0;" ::: "memory");
            __syncthreads();
            const float* hst = hst_grp + (c & 1) * 512;
            const float* wq  = wsm + (size_t)(kg * 128 + c * 16) * 48 + jp * 2;
#pragma unroll 4
            for (int kl = 0; kl < 16; kl++) {
                float4 h4 = *(const float4*)&hst[kl * 32 + b0];
                const float* w = wq + kl * 48;
                float2 wr = *(const float2*)(w);
                float2 wz = *(const float2*)(w + 16);
                float2 wn = *(const float2*)(w + 32);
                ar[0] = ffma2(bcast2(h4.x), wr, ar[0]);
                az[0] = ffma2(bcast2(h4.x), wz, az[0]);
                an[0] = ffma2(bcast2(h4.x), wn, an[0]);
                ar[1] = ffma2(bcast2(h4.y), wr, ar[1]);
                az[1] = ffma2(bcast2(h4.y), wz, az[1]);
                an[1] = ffma2(bcast2(h4.y), wn, an[1]);
                ar[2] = ffma2(bcast2(h4.z), wr, ar[2]);
                az[2] = ffma2(bcast2(h4.z), wz, az[2]);
                an[2] = ffma2(bcast2(h4.z), wn, an[2]);
                ar[3] = ffma2(bcast2(h4.w), wr, ar[3]);
                az[3] = ffma2(bcast2(h4.w), wz, az[3]);
                an[3] = ffma2(bcast2(h4.w), wn, an[3]);
            }
            __syncthreads();   // all reads of buf (c&1) done before re-staging it
            if (c + 2 < 8) {
                unsigned dst = hstg + (c & 1) * 2048 + t64 * 16;
                const float* src = hsrc + (c + 2) * 512 + t64 * 4;
                cpasync16(dst, src);
                cpasync16(dst + 1024, src + 256);
                asm volatile("cp.async.commit_group;" ::: "memory");
            }
        }

        // k-split reduction tree 8 -> 4 -> 2 -> 1 (red overlays staging; no cp.async pending)
        __syncthreads();
        if (kg >= 4) {
            int base = (kg - 4) * 768;
#pragma unroll
            for (int bi = 0; bi < 4; bi++) {
                red[base + (bi * 3 + 0) * 64 + t64] = ar[bi];
                red[base + (bi * 3 + 1) * 64 + t64] = az[bi];
                red[base + (bi * 3 + 2) * 64 + t64] = an[bi];
            }
        }
        __syncthreads();
        if (kg < 4) {
            int base = kg * 768;
#pragma unroll
            for (int bi = 0; bi < 4; bi++) {
                float2 vr = red[base + (bi * 3 + 0) * 64 + t64];
                float2 vz = red[base + (bi * 3 + 1) * 64 + t64];
                float2 vn = red[base + (bi * 3 + 2) * 64 + t64];
                ar[bi].x += vr.x; ar[bi].y += vr.y;
                az[bi].x += vz.x; az[bi].y += vz.y;
                an[bi].x += vn.x; an[bi].y += vn.y;
            }
        }
        __syncthreads();
        if (kg == 2 || kg == 3) {
            int base = (kg - 2) * 768;
#pragma unroll
            for (int bi = 0; bi < 4; bi++) {
                red[base + (bi * 3 + 0) * 64 + t64] = ar[bi];
                red[base + (bi * 3 + 1) * 64 + t64] = az[bi];
                red[base + (bi * 3 + 2) * 64 + t64] = an[bi];
            }
        }
        __syncthreads();
        if (kg < 2) {
            int base = kg * 768;
#pragma unroll
            for (int bi = 0; bi < 4; bi++) {
                float2 vr = red[base + (bi * 3 + 0) * 64 + t64];
                float2 vz = red[base + (bi * 3 + 1) * 64 + t64];
                float2 vn = red[base + (bi * 3 + 2) * 64 + t64];
                ar[bi].x += vr.x; ar[bi].y += vr.y;
                az[bi].x += vz.x; az[bi].y += vz.y;
                an[bi].x += vn.x; an[bi].y += vn.y;
            }
        }
        __syncthreads();
        if (kg == 1) {
#pragma unroll
            for (int bi = 0; bi < 4; bi++) {
                red[(bi * 3 + 0) * 64 + t64] = ar[bi];
                red[(bi * 3 + 1) * 64 + t64] = az[bi];
                red[(bi * 3 + 2) * 64 + t64] = an[bi];
            }
        }
        __syncthreads();
        if (kg == 0) {
            float h0n[4], h1n[4];
#pragma unroll
            for (int bi = 0; bi < 4; bi++) {
                float2 vr = red[(bi * 3 + 0) * 64 + t64];
                float2 vz = red[(bi * 3 + 1) * 64 + t64];
                float2 vn = red[(bi * 3 + 2) * 64 + t64];
                float sr0 = xr[bi].x + ar[bi].x + vr.x + br.x;
                float sr1 = xr[bi].y + ar[bi].y + vr.y + br.y;
                float sz0 = xz[bi].x + az[bi].x + vz.x + bz.x;
                float sz1 = xz[bi].y + az[bi].y + vz.y + bz.y;
                float sn0 = an[bi].x + vn.x + bn2.x;
                float sn1 = an[bi].y + vn.y + bn2.y;
                float r0 = sigmoidf_(sr0), r1 = sigmoidf_(sr1);
                float z0 = sigmoidf_(sz0), z1 = sigmoidf_(sz1);
                float n0 = tanhf(xn[bi].x + r0 * sn0);
                float n1 = tanhf(xn[bi].y + r1 * sn1);
                float hp0 = (bi == 0) ? hpa.x : (bi == 1) ? hpa.y : (bi == 2) ? hpa.z : hpa.w;
                float hp1 = (bi == 0) ? hpb.x : (bi == 1) ? hpb.y : (bi == 2) ? hpb.z : hpb.w;
                h0n[bi] = (1.f - z0) * n0 + z0 * hp0;
                h1n[bi] = (1.f - z1) * n1 + z1 * hp1;
            }
            float* hout = g_h[dir][(t + 1) & 1];
            *(float4*)(hout + j0 * BB + b0) = make_float4(h0n[0], h0n[1], h0n[2], h0n[3]);
            *(float4*)(hout + (j0 + 1) * BB + b0) = make_float4(h1n[0], h1n[1], h1n[2], h1n[3]);
            if (layer == 0) {
#pragma unroll
                for (int bi = 0; bi < 4; bi++)
                    *(float2*)(&g_out0[((size_t)(b0 + bi) * SS + s_sel) * H2 + dir * HH + j0]) =
                        make_float2(h0n[bi], h1n[bi]);
            }
        }

        dir_barrier(dir, (unsigned)(t + 1));
    }
}

// ---------------- zero hidden + barrier state (between layers) ----------------
__global__ void zero_h_k() {
    int i = blockIdx.x * blockDim.x + threadIdx.x;
    if (i < HH * BB) { g_h[0][0][i] = 0.f; g_h[1][0][i] = 0.f; }
    if (i < 2) { g_bar_count[i] = 0u; g_bar_gen[i] = 0u; }
}

// ---------------- final output ----------------
__global__ void finalize_k(float* __restrict__ out) {
    int i = blockIdx.x * blockDim.x + threadIdx.x;
    if (i < BB * H2) {
        int b = i >> 11, c = i & 2047;
        out[i] = (c < HH) ? g_h[0][0][c * BB + b] : g_h[1][0][(c - HH) * BB + b];
    }
}

// ---------------- host ----------------
extern "C" void kernel_launch(void* const* d_in, const int* in_sizes, int n_in,
                              void* d_out, int out_size)
{
    const float* x       = (const float*)d_in[0];
    const float* w_ih_f0 = (const float*)d_in[1];
    const float* w_hh_f0 = (const float*)d_in[2];
    const float* b_ih_f0 = (const float*)d_in[3];
    const float* b_hh_f0 = (const float*)d_in[4];
    const float* w_ih_b0 = (const float*)d_in[5];
    const float* w_hh_b0 = (const float*)d_in[6];
    const float* b_ih_b0 = (const float*)d_in[7];
    const float* b_hh_b0 = (const float*)d_in[8];
    const float* w_ih_f1 = (const float*)d_in[9];
    const float* w_hh_f1 = (const float*)d_in[10];
    const float* b_ih_f1 = (const float*)d_in[11];
    const float* b_hh_f1 = (const float*)d_in[12];
    const float* w_ih_b1 = (const float*)d_in[13];
    const float* w_hh_b1 = (const float*)d_in[14];
    const float* b_ih_b1 = (const float*)d_in[15];
    const float* b_hh_b1 = (const float*)d_in[16];
    float* out = (float*)d_out;

    cudaFuncSetAttribute(gru_layer, cudaFuncAttributeMaxDynamicSharedMemorySize,
                         GRU_SMEM_BYTES);

    float *wih0, *wih1, *gx, *out0;
    cudaGetSymbolAddress((void**)&wih0, g_wih0_t);
    cudaGetSymbolAddress((void**)&wih1, g_wih1_t);
    cudaGetSymbolAddress((void**)&gx,   g_gx);
    cudaGetSymbolAddress((void**)&out0, g_out0);

    float* wih0_f = wih0;
    float* wih0_b = wih0 + (size_t)II * G3;
    float* wih1_f = wih1;
    float* wih1_b = wih1 + (size_t)H2 * G3;
    float* gx_f = gx;
    float* gx_b = gx + (size_t)BB * SS * G3;

    dim3 ggrid(G3 / 128, (BB * SS) / 128, 2);

    transpose_ih<<<dim3(96, 64, 4), dim3(32, 8)>>>(
        w_ih_f0, w_ih_b0, w_ih_f1, w_ih_b1, wih0_f, wih0_b, wih1_f, wih1_b);
    prepack_whh<<<dim3(12288, 4), 256>>>(w_hh_f0, w_hh_b0, w_hh_f1, w_hh_b1);
    gemm_gx2<<<ggrid, 256>>>(x, SS * II, II, II, wih0_f, wih0_b,
                             b_ih_f0, b_ih_b0, gx_f, gx_b);
    gru_layer<<<dim3(64, 2), 512, GRU_SMEM_BYTES>>>(0, b_hh_f0, b_hh_b0);

    gemm_gx2<<<ggrid, 256>>>(out0, SS * H2, H2, H2, wih1_f, wih1_b,
                             b_ih_f1, b_ih_b1, gx_f, gx_b);
    zero_h_k<<<(HH * BB + 255) / 256, 256>>>();
    gru_layer<<<dim3(64, 2), 512, GRU_SMEM_BYTES>>>(1, b_hh_f1, b_hh_b1);

    finalize_k<<<(BB * H2 + 255) / 256, 256>>>(out);
}